// round 3
// baseline (speedup 1.0000x reference)
#include <cuda_runtime.h>
#include <cuda_fp16.h>

// Problem constants
#define H      1024
#define BB     2
#define CLS    30
#define EMBD   128
#define SEQ    1024
#define TSTEPS 1023      // n_seq - 1
#define G4     4096      // 4*H gate rows per layer
#define NROWS  12288     // 3 recurrent matrices * 4096 rows

// ---------------- persistent device state (static, no runtime alloc) ----------------
__device__ __half   d_w16[(size_t)NROWS * H];            // fp16 recurrent weights, row-major [row][k]
__device__ float    d_condW0[BB * G4];                   // cond @ Wih0[:, :H]^T + b_ih0 + b_hh0
__device__ float    d_embproj[CLS * G4];                 // emb  @ Wih0[:, H:]^T  per class
__device__ float    d_bias1[G4];                         // b_ih1 + b_hh1
__device__ float    d_gbuf[NROWS * 2];                   // dot results [row][batch]
__device__ float    d_h0[BB * H];
__device__ float    d_h1[BB * H];
__device__ float    d_h1hist[(size_t)TSTEPS * BB * H];   // layer-1 outputs for CE
__device__ unsigned d_flags[256 * 32];                   // barrier flags, 1 cache line / block
__device__ float    d_nll[TSTEPS * BB];

// ---------------- helpers ----------------
__device__ __forceinline__ float sigm(float x) { return 1.0f / (1.0f + __expf(-x)); }

__device__ __forceinline__ float2 h2f(unsigned u) {
    __half2 h;
    *reinterpret_cast<unsigned*>(&h) = u;
    return __half22float2(h);
}

// grid-wide barrier: per-block monotonic flag, all blocks poll all flags
__device__ __forceinline__ void gbar(unsigned target, int bk, int nb, int tid) {
    __syncthreads();
    if (tid == 0) {
        asm volatile("st.release.gpu.u32 [%0], %1;"
                     :: "l"(d_flags + bk * 32), "r"(target) : "memory");
    }
    if (tid < nb) {
        const unsigned* p = d_flags + tid * 32;
        unsigned v;
        while (true) {
            asm volatile("ld.acquire.gpu.u32 %0, [%1];" : "=r"(v) : "l"(p) : "memory");
            if (v >= target) break;
            __nanosleep(20);
        }
    }
    __syncthreads();
}

// one 1024-long fp16 dot against two batch vectors, warp-collective
__device__ __forceinline__ void dot_row(const uint4* __restrict__ wrow,
                                        const float (&hA)[32], const float (&hB)[32],
                                        int lane, float& o0, float& o1) {
    float s0 = 0.f, s1 = 0.f;
#pragma unroll
    for (int q = 0; q < 4; ++q) {
        uint4 w = wrow[q * 32 + lane];
        unsigned uu[4] = {w.x, w.y, w.z, w.w};
#pragma unroll
        for (int p = 0; p < 4; ++p) {
            float2 f = h2f(uu[p]);
            s0 = fmaf(f.x, hA[q * 8 + p * 2],     s0);
            s0 = fmaf(f.y, hA[q * 8 + p * 2 + 1], s0);
            s1 = fmaf(f.x, hB[q * 8 + p * 2],     s1);
            s1 = fmaf(f.y, hB[q * 8 + p * 2 + 1], s1);
        }
    }
#pragma unroll
    for (int off = 16; off > 0; off >>= 1) {
        s0 += __shfl_xor_sync(0xffffffffu, s0, off);
        s1 += __shfl_xor_sync(0xffffffffu, s1, off);
    }
    o0 = s0; o1 = s1;
}

// ---------------- prep kernels ----------------
__global__ void k_reset() {
    int i = blockIdx.x * blockDim.x + threadIdx.x;
    if (i < 256 * 32) d_flags[i] = 0u;
    if (i < BB * H) { d_h0[i] = 0.f; d_h1[i] = 0.f; }
}

__global__ void k_convert(const float* __restrict__ Whh0,
                          const float* __restrict__ Wih1,
                          const float* __restrict__ Whh1) {
    size_t stride = (size_t)gridDim.x * blockDim.x;
    size_t total = (size_t)NROWS * H;
    for (size_t i = (size_t)blockIdx.x * blockDim.x + threadIdx.x; i < total; i += stride) {
        size_t r = i >> 10;
        float v;
        if (r < 4096)      v = Whh0[i];
        else if (r < 8192) v = Wih1[i - (size_t)4096 * 1024];
        else               v = Whh1[i - (size_t)8192 * 1024];
        d_w16[i] = __float2half(v);
    }
}

__global__ void k_pre(const float* __restrict__ Wih0, const float* __restrict__ cond,
                      const float* __restrict__ emb,
                      const float* __restrict__ bih0, const float* __restrict__ bhh0,
                      const float* __restrict__ bih1, const float* __restrict__ bhh1) {
    int i = blockIdx.x * blockDim.x + threadIdx.x;
    if (i < BB * G4) {                 // condW0
        int b = i >> 12, j = i & 4095;
        const float* wr = Wih0 + (size_t)j * 1152;
        const float* cb = cond + b * H;
        float s = bih0[j] + bhh0[j];
        for (int k = 0; k < H; ++k) s += wr[k] * cb[k];
        d_condW0[i] = s;
    }
    int i2 = i - BB * G4;
    if (i2 >= 0 && i2 < CLS * G4) {    // embproj
        int c = i2 >> 12, j = i2 & 4095;
        const float* wr = Wih0 + (size_t)j * 1152 + H;
        const float* eb = emb + c * EMBD;
        float s = 0.f;
#pragma unroll 4
        for (int k = 0; k < EMBD; ++k) s += wr[k] * eb[k];
        d_embproj[i2] = s;
    }
    int i3 = i - (BB + CLS) * G4;
    if (i3 >= 0 && i3 < G4) d_bias1[i3] = bih1[i3] + bhh1[i3];
}

// ---------------- persistent recurrent kernel ----------------
__global__ void __launch_bounds__(256, 1)
k_recur(const long long* __restrict__ ids) {
    extern __shared__ __half sw[];
    const int tid = threadIdx.x, bk = blockIdx.x, nb = gridDim.x;
    const int lane = tid & 31, warp = tid >> 5;

    const int r0 = (int)(((long long)bk * NROWS) / nb);
    const int r1 = (int)(((long long)(bk + 1) * NROWS) / nb);
    const bool needH0 = (r0 < 2 * G4);
    const bool needH1 = (r1 > 2 * G4);

    // load this block's fp16 weight rows into SMEM (once)
    {
        const uint4* src = (const uint4*)(d_w16 + (size_t)r0 * H);
        uint4* dst = (uint4*)sw;
        const int nvec = (r1 - r0) * (H / 8);
        for (int i = tid; i < nvec; i += 256) dst[i] = src[i];
        __syncthreads();
    }
    const uint4* wbase = (const uint4*)sw;

    // static elementwise ownership: global thread id g
    const int g = bk * 256 + tid;
    const bool isL0 = (g < BB * H);
    const bool isL1 = (g >= BB * H) && (g < 2 * BB * H);
    const int b_el = (g >> 10) & 1;
    const int e_el = g & (H - 1);
    float cst = 0.f;   // per-owner cell state, lives in a register all 1023 steps

    // iteration-invariant elementwise prefetches
    float cw0 = 0, cw1 = 0, cw2 = 0, cw3 = 0;   // condW0 rows (L0) or bias1 rows (L1)
    if (isL0) {
        const float* cw = d_condW0 + b_el * G4;
        cw0 = cw[e_el]; cw1 = cw[e_el + 1024]; cw2 = cw[e_el + 2048]; cw3 = cw[e_el + 3072];
    } else if (isL1) {
        cw0 = d_bias1[e_el]; cw1 = d_bias1[e_el + 1024];
        cw2 = d_bias1[e_el + 2048]; cw3 = d_bias1[e_el + 3072];
    }

    float h0A[32], h0B[32], h1A[32], h1B[32];

    for (int it = 0; it < TSTEPS + 1; ++it) {
        const bool l0act = (it < TSTEPS);
        const bool l1act = (it >= 1);

        // refresh per-lane h slices (k = q*256 + lane*8 + j)
#pragma unroll
        for (int q = 0; q < 4; ++q) {
            const int kb = q * 256 + lane * 8;
            if (needH0) {
                float4 x0 = *(const float4*)(d_h0 + kb);
                float4 x1 = *(const float4*)(d_h0 + kb + 4);
                h0A[q*8+0]=x0.x; h0A[q*8+1]=x0.y; h0A[q*8+2]=x0.z; h0A[q*8+3]=x0.w;
                h0A[q*8+4]=x1.x; h0A[q*8+5]=x1.y; h0A[q*8+6]=x1.z; h0A[q*8+7]=x1.w;
                float4 y0 = *(const float4*)(d_h0 + H + kb);
                float4 y1 = *(const float4*)(d_h0 + H + kb + 4);
                h0B[q*8+0]=y0.x; h0B[q*8+1]=y0.y; h0B[q*8+2]=y0.z; h0B[q*8+3]=y0.w;
                h0B[q*8+4]=y1.x; h0B[q*8+5]=y1.y; h0B[q*8+6]=y1.z; h0B[q*8+7]=y1.w;
            }
            if (needH1) {
                float4 x0 = *(const float4*)(d_h1 + kb);
                float4 x1 = *(const float4*)(d_h1 + kb + 4);
                h1A[q*8+0]=x0.x; h1A[q*8+1]=x0.y; h1A[q*8+2]=x0.z; h1A[q*8+3]=x0.w;
                h1A[q*8+4]=x1.x; h1A[q*8+5]=x1.y; h1A[q*8+6]=x1.z; h1A[q*8+7]=x1.w;
                float4 y0 = *(const float4*)(d_h1 + H + kb);
                float4 y1 = *(const float4*)(d_h1 + H + kb + 4);
                h1B[q*8+0]=y0.x; h1B[q*8+1]=y0.y; h1B[q*8+2]=y0.z; h1B[q*8+3]=y0.w;
                h1B[q*8+4]=y1.x; h1B[q*8+5]=y1.y; h1B[q*8+6]=y1.z; h1B[q*8+7]=y1.w;
            }
        }

        // per-iteration elementwise prefetch (token embedding projection, L0 only)
        float ep0 = 0, ep1 = 0, ep2 = 0, ep3 = 0;
        if (isL0 && l0act) {
            int tok = (int)ids[b_el * SEQ + it];
            const float* ep = d_embproj + tok * G4;
            ep0 = ep[e_el]; ep1 = ep[e_el + 1024]; ep2 = ep[e_el + 2048]; ep3 = ep[e_el + 3072];
        }

        // --- dot phase: warp w owns rows r0+w, r0+w+8, ... ---
        for (int r = r0 + warp; r < r1; r += 8) {
            const bool act = (r < G4) ? l0act : l1act;
            if (!act) continue;
            const uint4* wrow = wbase + (size_t)(r - r0) * (H / 8);
            float s0, s1;
            if (r >= 2 * G4) dot_row(wrow, h1A, h1B, lane, s0, s1);
            else             dot_row(wrow, h0A, h0B, lane, s0, s1);
            if (lane == 0) *(float2*)&d_gbuf[2 * r] = make_float2(s0, s1);
        }

        gbar(2 * it + 1, bk, nb, tid);

        // --- elementwise phase ---
        if (isL0 && l0act) {
            float gi = d_gbuf[2 * (e_el)        + b_el] + cw0 + ep0;
            float gf = d_gbuf[2 * (e_el + 1024) + b_el] + cw1 + ep1;
            float gg = d_gbuf[2 * (e_el + 2048) + b_el] + cw2 + ep2;
            float go = d_gbuf[2 * (e_el + 3072) + b_el] + cw3 + ep3;
            cst = sigm(gf) * cst + sigm(gi) * tanhf(gg);
            d_h0[b_el * H + e_el] = sigm(go) * tanhf(cst);
        }
        if (isL1 && l1act) {
            float gi = d_gbuf[2*(G4 + e_el)        + b_el] + d_gbuf[2*(2*G4 + e_el)        + b_el] + cw0;
            float gf = d_gbuf[2*(G4 + e_el + 1024) + b_el] + d_gbuf[2*(2*G4 + e_el + 1024) + b_el] + cw1;
            float gg = d_gbuf[2*(G4 + e_el + 2048) + b_el] + d_gbuf[2*(2*G4 + e_el + 2048) + b_el] + cw2;
            float go = d_gbuf[2*(G4 + e_el + 3072) + b_el] + d_gbuf[2*(2*G4 + e_el + 3072) + b_el] + cw3;
            cst = sigm(gf) * cst + sigm(gi) * tanhf(gg);
            float h = sigm(go) * tanhf(cst);
            d_h1[b_el * H + e_el] = h;
            d_h1hist[(size_t)(it - 1) * BB * H + b_el * H + e_el] = h;
        }

        gbar(2 * it + 2, bk, nb, tid);
    }
}

// ---------------- CE kernels ----------------
__global__ void k_ce(const long long* __restrict__ ids,
                     const float* __restrict__ fcw, const float* __restrict__ fcb) {
    __shared__ float hs[H];
    __shared__ float lg[32];
    const int m = blockIdx.x;           // 0..2045
    const int b = m & 1, t = m >> 1;
    const int tid = threadIdx.x, lane = tid & 31, warp = tid >> 5;

    const float* hp = d_h1hist + (size_t)t * BB * H + b * H;
    for (int i = tid; i < H; i += 256) hs[i] = hp[i];
    __syncthreads();

    for (int c = warp; c < CLS; c += 8) {
        const float* wr = fcw + c * H;
        float s = 0.f;
        for (int k = lane; k < H; k += 32) s += wr[k] * hs[k];
#pragma unroll
        for (int off = 16; off > 0; off >>= 1) s += __shfl_xor_sync(0xffffffffu, s, off);
        if (lane == 0) lg[c] = s + fcb[c];
    }
    __syncthreads();

    if (tid == 0) {
        float mx = -1e30f;
        for (int c = 0; c < CLS; ++c) mx = fmaxf(mx, lg[c]);
        float se = 0.f;
        for (int c = 0; c < CLS; ++c) se += expf(lg[c] - mx);
        float lse = mx + logf(se);
        int tgt = (int)ids[b * SEQ + t + 1];
        d_nll[m] = lse - lg[tgt];
    }
}

__global__ void k_loss(const float* __restrict__ mask, float* __restrict__ out) {
    __shared__ float s1s[256], s2s[256];
    const int tid = threadIdx.x;
    float sn = 0.f, sm = 0.f;
    for (int i = tid; i < TSTEPS * BB; i += 256) sn += d_nll[i];
    for (int i = tid; i < BB * TSTEPS; i += 256) {
        int b = i / TSTEPS, t = i % TSTEPS;
        sm += mask[b * SEQ + t + 1];
    }
    s1s[tid] = sn; s2s[tid] = sm;
    __syncthreads();
    for (int o = 128; o > 0; o >>= 1) {
        if (tid < o) { s1s[tid] += s1s[tid + o]; s2s[tid] += s2s[tid + o]; }
        __syncthreads();
    }
    if (tid == 0) {
        float ce = s1s[0] / (float)(TSTEPS * BB);
        float masked = ce * s2s[0] / s2s[0];   // matches reference exactly (incl. mask==0 -> NaN)
        out[0] = ce + masked;
    }
}

// ---------------- launch ----------------
extern "C" void kernel_launch(void* const* d_in, const int* in_sizes, int n_in,
                              void* d_out, int out_size) {
    const long long* ids  = (const long long*)d_in[0];
    const float* mask     = (const float*)d_in[1];
    const float* cond     = (const float*)d_in[2];
    const float* emb      = (const float*)d_in[3];
    const float* Wih0     = (const float*)d_in[4];
    const float* Whh0     = (const float*)d_in[5];
    const float* bih0     = (const float*)d_in[6];
    const float* bhh0     = (const float*)d_in[7];
    const float* Wih1     = (const float*)d_in[8];
    const float* Whh1     = (const float*)d_in[9];
    const float* bih1     = (const float*)d_in[10];
    const float* bhh1     = (const float*)d_in[11];
    const float* fcw      = (const float*)d_in[12];
    const float* fcb      = (const float*)d_in[13];

    static int nb = 0;
    static size_t smem = 0;
    if (nb == 0) {
        int nsm = 0;
        cudaDeviceGetAttribute(&nsm, cudaDevAttrMultiProcessorCount, 0);
        if (nsm < 112) nsm = 112;   // keep per-block SMEM under the 227 KB limit
        if (nsm > 256) nsm = 256;
        nb = nsm;                    // one co-resident block per SM
        int rpb = (NROWS + nb - 1) / nb;
        smem = (size_t)rpb * (H * sizeof(__half));
        cudaFuncSetAttribute(k_recur, cudaFuncAttributeMaxDynamicSharedMemorySize, (int)smem);
    }

    k_reset<<<32, 256>>>();
    k_convert<<<4096, 256>>>(Whh0, Wih1, Whh1);
    k_pre<<<((BB + CLS + 1) * G4 + 255) / 256, 256>>>(Wih0, cond, emb, bih0, bhh0, bih1, bhh1);
    k_recur<<<nb, 256, smem>>>(ids);
    k_ce<<<TSTEPS * BB, 256>>>(ids, fcw, fcb);
    k_loss<<<1, 256>>>(mask, (float*)d_out);
}

// round 4
// speedup vs baseline: 1.0235x; 1.0235x over previous
#include <cuda_runtime.h>
#include <cuda_fp16.h>

// Problem constants
#define H      1024
#define BB     2
#define CLS    30
#define EMBD   128
#define SEQ    1024
#define TSTEPS 1023      // n_seq - 1
#define G4     4096      // 4*H gate rows per layer
#define NROWS  12288     // 3 recurrent matrices * 4096 rows

// ---------------- persistent device state (static, no runtime alloc) ----------------
__device__ __half   d_w16[(size_t)NROWS * H];            // fp16 recurrent weights, row-major [row][k]
__device__ float    d_condW0[BB * G4];                   // cond @ Wih0[:, :H]^T + b_ih0 + b_hh0
__device__ float    d_embproj[CLS * G4];                 // emb  @ Wih0[:, H:]^T  per class
__device__ float    d_bias1[G4];                         // b_ih1 + b_hh1
__device__ float    d_gbuf[NROWS * 2];                   // dot results [row][batch]
__device__ float    d_h0[BB * H];
__device__ float    d_h1[BB * H];
__device__ float    d_h1hist[(size_t)TSTEPS * BB * H];   // layer-1 outputs for CE
__device__ unsigned d_flags[256 * 32];                   // barrier flags, 1 cache line / block
__device__ float    d_nll[TSTEPS * BB];

// ---------------- helpers ----------------
__device__ __forceinline__ float sigm(float x) { return 1.0f / (1.0f + __expf(-x)); }

__device__ __forceinline__ float2 h2f(unsigned u) {
    __half2 h;
    *reinterpret_cast<unsigned*>(&h) = u;
    return __half22float2(h);
}

// grid-wide barrier: per-block monotonic flag, all blocks poll all flags
__device__ __forceinline__ void gbar(unsigned target, int bk, int nb, int tid) {
    __syncthreads();
    if (tid == 0) {
        asm volatile("st.release.gpu.u32 [%0], %1;"
                     :: "l"(d_flags + bk * 32), "r"(target) : "memory");
    }
    if (tid < nb) {
        const unsigned* p = d_flags + tid * 32;
        unsigned v;
        while (true) {
            asm volatile("ld.acquire.gpu.u32 %0, [%1];" : "=r"(v) : "l"(p) : "memory");
            if (v >= target) break;
            __nanosleep(20);
        }
    }
    __syncthreads();
}

// one 1024-long fp16 dot against two batch vectors, warp-collective
__device__ __forceinline__ void dot_row(const uint4* __restrict__ wrow,
                                        const float (&hA)[32], const float (&hB)[32],
                                        int lane, float& o0, float& o1) {
    float s0 = 0.f, s1 = 0.f;
#pragma unroll
    for (int q = 0; q < 4; ++q) {
        uint4 w = wrow[q * 32 + lane];
        unsigned uu[4] = {w.x, w.y, w.z, w.w};
#pragma unroll
        for (int p = 0; p < 4; ++p) {
            float2 f = h2f(uu[p]);
            s0 = fmaf(f.x, hA[q * 8 + p * 2],     s0);
            s0 = fmaf(f.y, hA[q * 8 + p * 2 + 1], s0);
            s1 = fmaf(f.x, hB[q * 8 + p * 2],     s1);
            s1 = fmaf(f.y, hB[q * 8 + p * 2 + 1], s1);
        }
    }
#pragma unroll
    for (int off = 16; off > 0; off >>= 1) {
        s0 += __shfl_xor_sync(0xffffffffu, s0, off);
        s1 += __shfl_xor_sync(0xffffffffu, s1, off);
    }
    o0 = s0; o1 = s1;
}

// ---------------- prep kernels ----------------
__global__ void k_reset() {
    int i = blockIdx.x * blockDim.x + threadIdx.x;
    if (i < 256 * 32) d_flags[i] = 0u;
    if (i < BB * H) { d_h0[i] = 0.f; d_h1[i] = 0.f; }
}

__global__ void k_convert(const float* __restrict__ Whh0,
                          const float* __restrict__ Wih1,
                          const float* __restrict__ Whh1) {
    size_t stride = (size_t)gridDim.x * blockDim.x;
    size_t total = (size_t)NROWS * H;
    for (size_t i = (size_t)blockIdx.x * blockDim.x + threadIdx.x; i < total; i += stride) {
        size_t r = i >> 10;
        float v;
        if (r < 4096)      v = Whh0[i];
        else if (r < 8192) v = Wih1[i - (size_t)4096 * 1024];
        else               v = Whh1[i - (size_t)8192 * 1024];
        d_w16[i] = __float2half(v);
    }
}

__global__ void k_pre(const float* __restrict__ Wih0, const float* __restrict__ cond,
                      const float* __restrict__ emb,
                      const float* __restrict__ bih0, const float* __restrict__ bhh0,
                      const float* __restrict__ bih1, const float* __restrict__ bhh1) {
    int i = blockIdx.x * blockDim.x + threadIdx.x;
    if (i < BB * G4) {                 // condW0
        int b = i >> 12, j = i & 4095;
        const float* wr = Wih0 + (size_t)j * 1152;
        const float* cb = cond + b * H;
        float s = bih0[j] + bhh0[j];
        for (int k = 0; k < H; ++k) s += wr[k] * cb[k];
        d_condW0[i] = s;
    }
    int i2 = i - BB * G4;
    if (i2 >= 0 && i2 < CLS * G4) {    // embproj
        int c = i2 >> 12, j = i2 & 4095;
        const float* wr = Wih0 + (size_t)j * 1152 + H;
        const float* eb = emb + c * EMBD;
        float s = 0.f;
#pragma unroll 4
        for (int k = 0; k < EMBD; ++k) s += wr[k] * eb[k];
        d_embproj[i2] = s;
    }
    int i3 = i - (BB + CLS) * G4;
    if (i3 >= 0 && i3 < G4) d_bias1[i3] = bih1[i3] + bhh1[i3];
}

// ---------------- persistent recurrent kernel ----------------
__global__ void __launch_bounds__(256, 1)
k_recur(const long long* __restrict__ ids) {
    extern __shared__ __half sw[];
    const int tid = threadIdx.x, bk = blockIdx.x, nb = gridDim.x;
    const int lane = tid & 31, warp = tid >> 5;

    const int r0 = (int)(((long long)bk * NROWS) / nb);
    const int r1 = (int)(((long long)(bk + 1) * NROWS) / nb);
    const bool needH0 = (r0 < 2 * G4);
    const bool needH1 = (r1 > 2 * G4);

    // load this block's fp16 weight rows into SMEM (once)
    {
        const uint4* src = (const uint4*)(d_w16 + (size_t)r0 * H);
        uint4* dst = (uint4*)sw;
        const int nvec = (r1 - r0) * (H / 8);
        for (int i = tid; i < nvec; i += 256) dst[i] = src[i];
        __syncthreads();
    }
    const uint4* wbase = (const uint4*)sw;

    // static elementwise ownership: global thread id g
    const int g = bk * 256 + tid;
    const bool isL0 = (g < BB * H);
    const bool isL1 = (g >= BB * H) && (g < 2 * BB * H);
    const int b_el = (g >> 10) & 1;
    const int e_el = g & (H - 1);
    float cst = 0.f;   // per-owner cell state, lives in a register all 1023 steps

    // iteration-invariant elementwise prefetches
    float cw0 = 0, cw1 = 0, cw2 = 0, cw3 = 0;   // condW0 rows (L0) or bias1 rows (L1)
    if (isL0) {
        const float* cw = d_condW0 + b_el * G4;
        cw0 = cw[e_el]; cw1 = cw[e_el + 1024]; cw2 = cw[e_el + 2048]; cw3 = cw[e_el + 3072];
    } else if (isL1) {
        cw0 = d_bias1[e_el]; cw1 = d_bias1[e_el + 1024];
        cw2 = d_bias1[e_el + 2048]; cw3 = d_bias1[e_el + 3072];
    }

    float h0A[32], h0B[32], h1A[32], h1B[32];

    for (int it = 0; it < TSTEPS + 1; ++it) {
        const bool l0act = (it < TSTEPS);
        const bool l1act = (it >= 1);

        // refresh per-lane h slices (k = q*256 + lane*8 + j)
#pragma unroll
        for (int q = 0; q < 4; ++q) {
            const int kb = q * 256 + lane * 8;
            if (needH0) {
                float4 x0 = *(const float4*)(d_h0 + kb);
                float4 x1 = *(const float4*)(d_h0 + kb + 4);
                h0A[q*8+0]=x0.x; h0A[q*8+1]=x0.y; h0A[q*8+2]=x0.z; h0A[q*8+3]=x0.w;
                h0A[q*8+4]=x1.x; h0A[q*8+5]=x1.y; h0A[q*8+6]=x1.z; h0A[q*8+7]=x1.w;
                float4 y0 = *(const float4*)(d_h0 + H + kb);
                float4 y1 = *(const float4*)(d_h0 + H + kb + 4);
                h0B[q*8+0]=y0.x; h0B[q*8+1]=y0.y; h0B[q*8+2]=y0.z; h0B[q*8+3]=y0.w;
                h0B[q*8+4]=y1.x; h0B[q*8+5]=y1.y; h0B[q*8+6]=y1.z; h0B[q*8+7]=y1.w;
            }
            if (needH1) {
                float4 x0 = *(const float4*)(d_h1 + kb);
                float4 x1 = *(const float4*)(d_h1 + kb + 4);
                h1A[q*8+0]=x0.x; h1A[q*8+1]=x0.y; h1A[q*8+2]=x0.z; h1A[q*8+3]=x0.w;
                h1A[q*8+4]=x1.x; h1A[q*8+5]=x1.y; h1A[q*8+6]=x1.z; h1A[q*8+7]=x1.w;
                float4 y0 = *(const float4*)(d_h1 + H + kb);
                float4 y1 = *(const float4*)(d_h1 + H + kb + 4);
                h1B[q*8+0]=y0.x; h1B[q*8+1]=y0.y; h1B[q*8+2]=y0.z; h1B[q*8+3]=y0.w;
                h1B[q*8+4]=y1.x; h1B[q*8+5]=y1.y; h1B[q*8+6]=y1.z; h1B[q*8+7]=y1.w;
            }
        }

        // per-iteration elementwise prefetch (token embedding projection, L0 only)
        float ep0 = 0, ep1 = 0, ep2 = 0, ep3 = 0;
        if (isL0 && l0act) {
            int tok = (int)ids[b_el * SEQ + it];
            const float* ep = d_embproj + tok * G4;
            ep0 = ep[e_el]; ep1 = ep[e_el + 1024]; ep2 = ep[e_el + 2048]; ep3 = ep[e_el + 3072];
        }

        // --- dot phase: warp w owns rows r0+w, r0+w+8, ... ---
        for (int r = r0 + warp; r < r1; r += 8) {
            const bool act = (r < G4) ? l0act : l1act;
            if (!act) continue;
            const uint4* wrow = wbase + (size_t)(r - r0) * (H / 8);
            float s0, s1;
            if (r >= 2 * G4) dot_row(wrow, h1A, h1B, lane, s0, s1);
            else             dot_row(wrow, h0A, h0B, lane, s0, s1);
            if (lane == 0) *(float2*)&d_gbuf[2 * r] = make_float2(s0, s1);
        }

        gbar(2 * it + 1, bk, nb, tid);

        // --- elementwise phase ---
        if (isL0 && l0act) {
            float gi = d_gbuf[2 * (e_el)        + b_el] + cw0 + ep0;
            float gf = d_gbuf[2 * (e_el + 1024) + b_el] + cw1 + ep1;
            float gg = d_gbuf[2 * (e_el + 2048) + b_el] + cw2 + ep2;
            float go = d_gbuf[2 * (e_el + 3072) + b_el] + cw3 + ep3;
            cst = sigm(gf) * cst + sigm(gi) * tanhf(gg);
            d_h0[b_el * H + e_el] = sigm(go) * tanhf(cst);
        }
        if (isL1 && l1act) {
            float gi = d_gbuf[2*(G4 + e_el)        + b_el] + d_gbuf[2*(2*G4 + e_el)        + b_el] + cw0;
            float gf = d_gbuf[2*(G4 + e_el + 1024) + b_el] + d_gbuf[2*(2*G4 + e_el + 1024) + b_el] + cw1;
            float gg = d_gbuf[2*(G4 + e_el + 2048) + b_el] + d_gbuf[2*(2*G4 + e_el + 2048) + b_el] + cw2;
            float go = d_gbuf[2*(G4 + e_el + 3072) + b_el] + d_gbuf[2*(2*G4 + e_el + 3072) + b_el] + cw3;
            cst = sigm(gf) * cst + sigm(gi) * tanhf(gg);
            float h = sigm(go) * tanhf(cst);
            d_h1[b_el * H + e_el] = h;
            d_h1hist[(size_t)(it - 1) * BB * H + b_el * H + e_el] = h;
        }

        gbar(2 * it + 2, bk, nb, tid);
    }
}

// ---------------- CE kernels ----------------
__global__ void k_ce(const long long* __restrict__ ids,
                     const float* __restrict__ fcw, const float* __restrict__ fcb) {
    __shared__ float hs[H];
    __shared__ float lg[32];
    const int m = blockIdx.x;           // 0..2045
    const int b = m & 1, t = m >> 1;
    const int tid = threadIdx.x, lane = tid & 31, warp = tid >> 5;

    const float* hp = d_h1hist + (size_t)t * BB * H + b * H;
    for (int i = tid; i < H; i += 256) hs[i] = hp[i];
    __syncthreads();

    for (int c = warp; c < CLS; c += 8) {
        const float* wr = fcw + c * H;
        float s = 0.f;
        for (int k = lane; k < H; k += 32) s += wr[k] * hs[k];
#pragma unroll
        for (int off = 16; off > 0; off >>= 1) s += __shfl_xor_sync(0xffffffffu, s, off);
        if (lane == 0) lg[c] = s + fcb[c];
    }
    __syncthreads();

    if (tid == 0) {
        float mx = -1e30f;
        for (int c = 0; c < CLS; ++c) mx = fmaxf(mx, lg[c]);
        float se = 0.f;
        for (int c = 0; c < CLS; ++c) se += expf(lg[c] - mx);
        float lse = mx + logf(se);
        int tgt = (int)ids[b * SEQ + t + 1];
        d_nll[m] = lse - lg[tgt];
    }
}

__global__ void k_loss(const float* __restrict__ mask, float* __restrict__ out) {
    __shared__ float s1s[256], s2s[256];
    const int tid = threadIdx.x;
    float sn = 0.f, sm = 0.f;
    for (int i = tid; i < TSTEPS * BB; i += 256) sn += d_nll[i];
    for (int i = tid; i < BB * TSTEPS; i += 256) {
        int b = i / TSTEPS, t = i % TSTEPS;
        sm += mask[b * SEQ + t + 1];
    }
    s1s[tid] = sn; s2s[tid] = sm;
    __syncthreads();
    for (int o = 128; o > 0; o >>= 1) {
        if (tid < o) { s1s[tid] += s1s[tid + o]; s2s[tid] += s2s[tid + o]; }
        __syncthreads();
    }
    if (tid == 0) {
        float ce = s1s[0] / (float)(TSTEPS * BB);
        float masked = ce * s2s[0] / s2s[0];   // matches reference exactly (incl. mask==0 -> NaN)
        out[0] = ce + masked;
    }
}

// ---------------- launch ----------------
extern "C" void kernel_launch(void* const* d_in, const int* in_sizes, int n_in,
                              void* d_out, int out_size) {
    const long long* ids  = (const long long*)d_in[0];
    const float* mask     = (const float*)d_in[1];
    const float* cond     = (const float*)d_in[2];
    const float* emb      = (const float*)d_in[3];
    const float* Wih0     = (const float*)d_in[4];
    const float* Whh0     = (const float*)d_in[5];
    const float* bih0     = (const float*)d_in[6];
    const float* bhh0     = (const float*)d_in[7];
    const float* Wih1     = (const float*)d_in[8];
    const float* Whh1     = (const float*)d_in[9];
    const float* bih1     = (const float*)d_in[10];
    const float* bhh1     = (const float*)d_in[11];
    const float* fcw      = (const float*)d_in[12];
    const float* fcb      = (const float*)d_in[13];

    static int nb = 0;
    static size_t smem = 0;
    if (nb == 0) {
        int nsm = 0;
        cudaDeviceGetAttribute(&nsm, cudaDevAttrMultiProcessorCount, 0);
        if (nsm < 112) nsm = 112;   // keep per-block SMEM under the 227 KB limit
        if (nsm > 256) nsm = 256;
        nb = nsm;                    // one co-resident block per SM
        int rpb = (NROWS + nb - 1) / nb;
        smem = (size_t)rpb * (H * sizeof(__half));
        cudaFuncSetAttribute(k_recur, cudaFuncAttributeMaxDynamicSharedMemorySize, (int)smem);
    }

    k_reset<<<32, 256>>>();
    k_convert<<<4096, 256>>>(Whh0, Wih1, Whh1);
    k_pre<<<((BB + CLS + 1) * G4 + 255) / 256, 256>>>(Wih0, cond, emb, bih0, bhh0, bih1, bhh1);
    k_recur<<<nb, 256, smem>>>(ids);
    k_ce<<<TSTEPS * BB, 256>>>(ids, fcw, fcb);
    k_loss<<<1, 256>>>(mask, (float*)d_out);
}

// round 6
// speedup vs baseline: 1.5969x; 1.5603x over previous
#include <cuda_runtime.h>
#include <cuda_fp16.h>

// Problem constants
#define H      1024
#define BB     2
#define CLS    30
#define EMBD   128
#define SEQ    1024
#define TSTEPS 1023      // n_seq - 1
#define G4     4096      // 4*H gate rows per layer

// Block partition: gate rows of an element live in ONE block.
#define NBL0   43        // L0 blocks: 24 elements x 4 gate rows = 96 rows
#define EL0    24
#define NBL1   86        // L1 blocks: 12 elements x 8 rows (4 Wih1 + 4 Whh1) = 96
#define EL1    12
#define NB     (NBL0 + NBL1)   // 129 blocks, one per SM, co-resident
#define RPB    96
#define SMEM_W_BYTES ((size_t)RPB * H * sizeof(__half))
#define SMEM_TOTAL   (SMEM_W_BYTES + RPB * 2 * sizeof(float))

// ---------------- persistent device state ----------------
__device__ float    d_condW0[BB * G4];                   // cond @ Wih0[:, :H]^T + b_ih0 + b_hh0
__device__ float    d_embproj[CLS * G4];                 // emb  @ Wih0[:, H:]^T per class
__device__ float    d_bias1[G4];                         // b_ih1 + b_hh1
__device__ float    d_h0[BB * H];
__device__ float    d_h1[BB * H];
__device__ float    d_h1hist[(size_t)TSTEPS * BB * H];   // layer-1 outputs for CE
__device__ unsigned d_flags[NB * 32];                    // barrier flags, 1 line per block
__device__ float    d_nll[TSTEPS * BB];

// ---------------- helpers ----------------
__device__ __forceinline__ float tanhap(float x) {
    float y; asm("tanh.approx.f32 %0, %1;" : "=f"(y) : "f"(x)); return y;
}
__device__ __forceinline__ float sigap(float x) { return 0.5f * tanhap(0.5f * x) + 0.5f; }

__device__ __forceinline__ unsigned long long pk(float x, float y) {
    unsigned long long r;
    asm("mov.b64 %0, {%1, %2};" : "=l"(r) : "r"(__float_as_uint(x)), "r"(__float_as_uint(y)));
    return r;
}
__device__ __forceinline__ float2 upk(unsigned long long v) {
    unsigned lo, hi;
    asm("mov.b64 {%0, %1}, %2;" : "=r"(lo), "=r"(hi) : "l"(v));
    return make_float2(__uint_as_float(lo), __uint_as_float(hi));
}
// packed fp32x2 FMA (Blackwell sm_100+): acc += a * b elementwise on both lanes
__device__ __forceinline__ void fma2(unsigned long long& c, unsigned long long a, unsigned long long b) {
    asm("fma.rn.f32x2 %0, %1, %2, %0;" : "+l"(c) : "l"(a), "l"(b));
}

// grid-wide barrier: per-block monotonic flag, blocks poll all flags.
// Spin is BOUNDED (2^18 polls ~ tens of ms): a sync bug degrades to a wrong
// answer + bench diagnostics instead of a container-killing hang.
__device__ __forceinline__ void gbar(unsigned target, int bk, int tid) {
    __syncthreads();
    if (tid == 0) {
        asm volatile("st.release.gpu.u32 [%0], %1;"
                     :: "l"(d_flags + bk * 32), "r"(target) : "memory");
    }
    if (tid < NB) {
        const unsigned* p = d_flags + tid * 32;
        unsigned v; unsigned spins = 0;
        do {
            asm volatile("ld.acquire.gpu.u32 %0, [%1];" : "=r"(v) : "l"(p) : "memory");
        } while (v < target && ++spins < (1u << 18));
    }
    __syncthreads();
}

// ---------------- prep kernels ----------------
__global__ void k_reset() {
    int i = blockIdx.x * blockDim.x + threadIdx.x;
    if (i < NB * 32) d_flags[i] = 0u;
    if (i < BB * H) { d_h0[i] = 0.f; d_h1[i] = 0.f; }
}

__global__ void k_pre(const float* __restrict__ Wih0, const float* __restrict__ cond,
                      const float* __restrict__ emb,
                      const float* __restrict__ bih0, const float* __restrict__ bhh0,
                      const float* __restrict__ bih1, const float* __restrict__ bhh1) {
    int i = blockIdx.x * blockDim.x + threadIdx.x;
    if (i < BB * G4) {                 // condW0
        int b = i >> 12, j = i & 4095;
        const float* wr = Wih0 + (size_t)j * 1152;
        const float* cb = cond + b * H;
        float s = bih0[j] + bhh0[j];
#pragma unroll 4
        for (int k = 0; k < H; ++k) s += wr[k] * cb[k];
        d_condW0[i] = s;
    }
    int i2 = i - BB * G4;
    if (i2 >= 0 && i2 < CLS * G4) {    // embproj
        int c = i2 >> 12, j = i2 & 4095;
        const float* wr = Wih0 + (size_t)j * 1152 + H;
        const float* eb = emb + c * EMBD;
        float s = 0.f;
#pragma unroll 4
        for (int k = 0; k < EMBD; ++k) s += wr[k] * eb[k];
        d_embproj[i2] = s;
    }
    int i3 = i - (BB + CLS) * G4;
    if (i3 >= 0 && i3 < G4) d_bias1[i3] = bih1[i3] + bhh1[i3];
}

// ---------------- persistent recurrent kernel ----------------
// L0 block bk<NBL0: elements e = bk*24+j (j<24); SMEM slot s = j*4+g -> Whh0[g*1024+e]
// L1 block: elements e = lb*12+j (j<12); slots [0,48): Wih1 (input h0, warps 0-3),
//                                        slots [48,96): Whh1 (input h1, warps 4-7)
__global__ void __launch_bounds__(256, 1)
k_recur(const long long* __restrict__ ids,
        const float* __restrict__ Whh0,
        const float* __restrict__ Wih1,
        const float* __restrict__ Whh1) {
    extern __shared__ char smem[];
    __half* sw = (__half*)smem;
    float (*gres)[2] = (float(*)[2])(smem + SMEM_W_BYTES);

    const int tid = threadIdx.x, bk = blockIdx.x;
    const int lane = tid & 31, warp = tid >> 5;
    const bool isL1 = (bk >= NBL0);
    const int lb = isL1 ? (bk - NBL0) : bk;
    const int ebase = isL1 ? lb * EL1 : lb * EL0;

    // ---- prologue: gather fp32 weight rows -> fp16 SMEM (once) ----
    for (int i = tid; i < RPB * 256; i += 256) {
        int s = i >> 8, c = i & 255;     // c = float4 index within the 1024-wide row
        int g, e; const float* src;
        if (!isL1)      { g = s & 3;        e = ebase + (s >> 2);        src = Whh0; }
        else if (s < 48){ g = s & 3;        e = ebase + (s >> 2);        src = Wih1; }
        else            { int s2 = s - 48; g = s2 & 3; e = ebase + (s2 >> 2); src = Whh1; }
        __half2 out0, out1;
        if (e < H) {
            float4 v = *(const float4*)(src + (size_t)(g * 1024 + e) * H + c * 4);
            out0 = __floats2half2_rn(v.x, v.y);
            out1 = __floats2half2_rn(v.z, v.w);
        } else {
            out0 = __floats2half2_rn(0.f, 0.f); out1 = out0;
        }
        uint2 packed;
        packed.x = *reinterpret_cast<unsigned*>(&out0);
        packed.y = *reinterpret_cast<unsigned*>(&out1);
        *(uint2*)(sw + (size_t)s * H + c * 4) = packed;
    }

    // ---- elementwise task setup (thread tid handles (j = tid/2, batch = tid&1)) ----
    const int nel = isL1 ? EL1 : EL0;
    const int jt = tid >> 1, bt = tid & 1;
    const int et = ebase + jt;
    const bool task = (jt < nel) && (et < H);
    float cw0 = 0, cw1 = 0, cw2 = 0, cw3 = 0;
    if (task) {
        if (!isL1) {
            const float* cw = d_condW0 + bt * G4 + et;
            cw0 = cw[0]; cw1 = cw[1024]; cw2 = cw[2048]; cw3 = cw[3072];
        } else {
            cw0 = d_bias1[et];        cw1 = d_bias1[et + 1024];
            cw2 = d_bias1[et + 2048]; cw3 = d_bias1[et + 3072];
        }
    }
    float cst = 0.f;   // cell state, register-resident for the whole sequence
    const float* hsrc = (!isL1 || warp < 4) ? d_h0 : d_h1;  // warp-pure input layer
    __syncthreads();   // SMEM weights ready

    unsigned long long hA[16], hB[16];   // lane's k-slice, packed f32x2 pairs

    for (int it = 0; it <= TSTEPS; ++it) {
        const bool act = isL1 ? (it >= 1) : (it < TSTEPS);

        // per-step elementwise prefetch (token projection, L0 only)
        float ep0 = 0, ep1 = 0, ep2 = 0, ep3 = 0;
        if (act && task && !isL1) {
            int tok = (int)ids[bt * SEQ + it];
            const float* ep = d_embproj + tok * G4 + et;
            ep0 = ep[0]; ep1 = ep[1024]; ep2 = ep[2048]; ep3 = ep[3072];
        }

        if (act) {
            // refresh h slice: k = q*256 + lane*8 + j
#pragma unroll
            for (int q = 0; q < 4; ++q) {
                int kb = q * 256 + lane * 8;
                float4 a0 = *(const float4*)(hsrc + kb);
                float4 a1 = *(const float4*)(hsrc + kb + 4);
                hA[q*4+0] = pk(a0.x, a0.y); hA[q*4+1] = pk(a0.z, a0.w);
                hA[q*4+2] = pk(a1.x, a1.y); hA[q*4+3] = pk(a1.z, a1.w);
                float4 b0 = *(const float4*)(hsrc + H + kb);
                float4 b1 = *(const float4*)(hsrc + H + kb + 4);
                hB[q*4+0] = pk(b0.x, b0.y); hB[q*4+1] = pk(b0.z, b0.w);
                hB[q*4+2] = pk(b1.x, b1.y); hB[q*4+3] = pk(b1.z, b1.w);
            }

            // dot phase: 12 rows per warp, processed in pairs for ILP
#pragma unroll 2
            for (int rp = 0; rp < 6; ++rp) {
                const int s0 = warp * 12 + rp * 2;
                const uint4* w0 = (const uint4*)(sw + (size_t)s0 * H);
                const uint4* w1 = (const uint4*)(sw + (size_t)(s0 + 1) * H);
                unsigned long long aA0 = 0, aB0 = 0, aA1 = 0, aB1 = 0;
#pragma unroll
                for (int q = 0; q < 4; ++q) {
                    uint4 u0 = w0[q * 32 + lane];
                    uint4 u1 = w1[q * 32 + lane];
#pragma unroll
                    for (int p = 0; p < 4; ++p) {
                        unsigned c0 = (&u0.x)[p], c1 = (&u1.x)[p];
                        float2 f0 = __half22float2(*reinterpret_cast<__half2*>(&c0));
                        float2 f1 = __half22float2(*reinterpret_cast<__half2*>(&c1));
                        unsigned long long wp0 = pk(f0.x, f0.y);
                        unsigned long long wp1 = pk(f1.x, f1.y);
                        fma2(aA0, wp0, hA[q*4+p]); fma2(aB0, wp0, hB[q*4+p]);
                        fma2(aA1, wp1, hA[q*4+p]); fma2(aB1, wp1, hB[q*4+p]);
                    }
                }
                float2 xA0 = upk(aA0), xB0 = upk(aB0), xA1 = upk(aA1), xB1 = upk(aB1);
                float v0 = xA0.x + xA0.y, v1 = xB0.x + xB0.y;
                float v2 = xA1.x + xA1.y, v3 = xB1.x + xB1.y;
#pragma unroll
                for (int off = 16; off > 0; off >>= 1) {
                    v0 += __shfl_xor_sync(0xffffffffu, v0, off);
                    v1 += __shfl_xor_sync(0xffffffffu, v1, off);
                    v2 += __shfl_xor_sync(0xffffffffu, v2, off);
                    v3 += __shfl_xor_sync(0xffffffffu, v3, off);
                }
                if (lane == 0) {
                    gres[s0][0] = v0;     gres[s0][1] = v1;
                    gres[s0 + 1][0] = v2; gres[s0 + 1][1] = v3;
                }
            }
        }
        __syncthreads();   // gres visible block-wide

        // elementwise phase (block-local gate gather, no global round trip)
        if (act && task) {
            const int j4 = jt * 4;
            float gi, gf, gg, go;
            if (!isL1) {
                gi = gres[j4 + 0][bt] + cw0 + ep0;
                gf = gres[j4 + 1][bt] + cw1 + ep1;
                gg = gres[j4 + 2][bt] + cw2 + ep2;
                go = gres[j4 + 3][bt] + cw3 + ep3;
            } else {
                gi = gres[j4 + 0][bt] + gres[48 + j4 + 0][bt] + cw0;
                gf = gres[j4 + 1][bt] + gres[48 + j4 + 1][bt] + cw1;
                gg = gres[j4 + 2][bt] + gres[48 + j4 + 2][bt] + cw2;
                go = gres[j4 + 3][bt] + gres[48 + j4 + 3][bt] + cw3;
            }
            cst = sigap(gf) * cst + sigap(gi) * tanhap(gg);
            float h = sigap(go) * tanhap(cst);
            if (!isL1) {
                d_h0[bt * H + et] = h;
            } else {
                d_h1[bt * H + et] = h;
                d_h1hist[(size_t)(it - 1) * (BB * H) + bt * H + et] = h;
            }
        }

        if (it < TSTEPS) gbar(it + 1, bk, tid);   // single barrier per step
    }
}

// ---------------- CE kernels ----------------
__global__ void k_ce(const long long* __restrict__ ids,
                     const float* __restrict__ fcw, const float* __restrict__ fcb) {
    __shared__ float hs[H];
    __shared__ float lg[32];
    const int m = blockIdx.x;           // 0..2045
    const int b = m & 1, t = m >> 1;
    const int tid = threadIdx.x, lane = tid & 31, warp = tid >> 5;

    const float* hp = d_h1hist + (size_t)t * BB * H + b * H;
    for (int i = tid; i < H; i += 256) hs[i] = hp[i];
    __syncthreads();

    for (int c = warp; c < CLS; c += 8) {
        const float* wr = fcw + c * H;
        float s = 0.f;
        for (int k = lane; k < H; k += 32) s += wr[k] * hs[k];
#pragma unroll
        for (int off = 16; off > 0; off >>= 1) s += __shfl_xor_sync(0xffffffffu, s, off);
        if (lane == 0) lg[c] = s + fcb[c];
    }
    __syncthreads();

    if (tid == 0) {
        float mx = -1e30f;
        for (int c = 0; c < CLS; ++c) mx = fmaxf(mx, lg[c]);
        float se = 0.f;
        for (int c = 0; c < CLS; ++c) se += expf(lg[c] - mx);
        float lse = mx + logf(se);
        int tgt = (int)ids[b * SEQ + t + 1];
        d_nll[m] = lse - lg[tgt];
    }
}

__global__ void k_loss(const float* __restrict__ mask, float* __restrict__ out) {
    __shared__ float s1s[256], s2s[256];
    const int tid = threadIdx.x;
    float sn = 0.f, sm = 0.f;
    for (int i = tid; i < TSTEPS * BB; i += 256) sn += d_nll[i];
    for (int i = tid; i < BB * TSTEPS; i += 256) {
        int b = i / TSTEPS, t = i % TSTEPS;
        sm += mask[b * SEQ + t + 1];
    }
    s1s[tid] = sn; s2s[tid] = sm;
    __syncthreads();
    for (int o = 128; o > 0; o >>= 1) {
        if (tid < o) { s1s[tid] += s1s[tid + o]; s2s[tid] += s2s[tid + o]; }
        __syncthreads();
    }
    if (tid == 0) {
        float ce = s1s[0] / (float)(TSTEPS * BB);
        float masked = ce * s2s[0] / s2s[0];   // matches reference (incl. mask==0 -> NaN)
        out[0] = ce + masked;
    }
}

// ---------------- launch ----------------
extern "C" void kernel_launch(void* const* d_in, const int* in_sizes, int n_in,
                              void* d_out, int out_size) {
    const long long* ids  = (const long long*)d_in[0];
    const float* mask     = (const float*)d_in[1];
    const float* cond     = (const float*)d_in[2];
    const float* emb      = (const float*)d_in[3];
    const float* Wih0     = (const float*)d_in[4];
    const float* Whh0     = (const float*)d_in[5];
    const float* bih0     = (const float*)d_in[6];
    const float* bhh0     = (const float*)d_in[7];
    const float* Wih1     = (const float*)d_in[8];
    const float* Whh1     = (const float*)d_in[9];
    const float* bih1     = (const float*)d_in[10];
    const float* bhh1     = (const float*)d_in[11];
    const float* fcw      = (const float*)d_in[12];
    const float* fcb      = (const float*)d_in[13];

    static bool init = false;
    if (!init) {
        cudaFuncSetAttribute(k_recur, cudaFuncAttributeMaxDynamicSharedMemorySize,
                             (int)SMEM_TOTAL);
        init = true;
    }

    k_reset<<<32, 256>>>();
    k_pre<<<((BB + CLS + 1) * G4 + 255) / 256, 256>>>(Wih0, cond, emb, bih0, bhh0, bih1, bhh1);
    k_recur<<<NB, 256, SMEM_TOTAL>>>(ids, Whh0, Wih1, Whh1);
    k_ce<<<TSTEPS * BB, 256>>>(ids, fcw, fcb);
    k_loss<<<1, 256>>>(mask, (float*)d_out);
}

// round 7
// speedup vs baseline: 1.6251x; 1.0176x over previous
#include <cuda_runtime.h>
#include <cuda_fp16.h>

// Problem constants
#define H      1024
#define BB     2
#define CLS    30
#define EMBD   128
#define SEQ    1024
#define TSTEPS 1023      // n_seq - 1
#define G4     4096      // 4*H gate rows per layer

// Block partition: gate rows of an element live in ONE block.
#define NBL0   43        // L0 blocks: 24 elements x 4 gate rows = 96 rows
#define EL0    24
#define NBL1   86        // L1 blocks: 12 elements x 8 rows (4 Wih1 + 4 Whh1) = 96
#define EL1    12
#define NB     (NBL0 + NBL1)   // 129 blocks, one per SM, co-resident
#define RPB    96
#define SMEM_W_BYTES ((size_t)RPB * H * sizeof(__half))
#define SMEM_TOTAL   (SMEM_W_BYTES + RPB * 2 * sizeof(float))

// ---------------- persistent device state ----------------
__device__ float    d_condW0[BB * G4];                   // cond @ Wih0[:, :H]^T + b_ih0 + b_hh0
__device__ float    d_embproj[CLS * G4];                 // emb  @ Wih0[:, H:]^T per class
__device__ float    d_bias1[G4];                         // b_ih1 + b_hh1
__device__ float    d_h0[2][BB * H];                     // double-buffered layer-0 hidden
__device__ float    d_h1[2][BB * H];                     // double-buffered layer-1 hidden
__device__ float    d_h1hist[(size_t)TSTEPS * BB * H];   // layer-1 outputs for CE
__device__ unsigned d_flags[NB * 32];                    // per-block monotonic progress flags
__device__ float    d_nll[TSTEPS * BB];

// ---------------- helpers ----------------
__device__ __forceinline__ float tanhap(float x) {
    float y; asm("tanh.approx.f32 %0, %1;" : "=f"(y) : "f"(x)); return y;
}
__device__ __forceinline__ float sigap(float x) { return 0.5f * tanhap(0.5f * x) + 0.5f; }

__device__ __forceinline__ unsigned long long pk(float x, float y) {
    unsigned long long r;
    asm("mov.b64 %0, {%1, %2};" : "=l"(r) : "r"(__float_as_uint(x)), "r"(__float_as_uint(y)));
    return r;
}
__device__ __forceinline__ float2 upk(unsigned long long v) {
    unsigned lo, hi;
    asm("mov.b64 {%0, %1}, %2;" : "=r"(lo), "=r"(hi) : "l"(v));
    return make_float2(__uint_as_float(lo), __uint_as_float(hi));
}
// packed fp32x2 FMA (Blackwell sm_100+): acc += a * b elementwise on both lanes
__device__ __forceinline__ void fma2(unsigned long long& c, unsigned long long a, unsigned long long b) {
    asm("fma.rn.f32x2 %0, %1, %2, %0;" : "+l"(c) : "l"(a), "l"(b));
}

// Decoupled wait: threads [0,NBL0) poll L0 flags against tgt0; threads
// [64, 64+NBL1) poll L1 flags against tgt1. Bounded spin: a sync bug degrades
// to a wrong answer + diagnostics instead of a container-killing hang.
__device__ __forceinline__ void wait2(int tgt0, int tgt1, int tid) {
    int fi = -1, tg = 0;
    if (tid < NBL0)                        { fi = tid;               tg = tgt0; }
    else if (tid >= 64 && tid < 64 + NBL1) { fi = NBL0 + (tid - 64); tg = tgt1; }
    if (fi >= 0 && tg > 0) {
        const unsigned* p = d_flags + fi * 32;
        unsigned v; unsigned spins = 0;
        do {
            asm volatile("ld.acquire.gpu.u32 %0, [%1];" : "=r"(v) : "l"(p) : "memory");
        } while ((int)v < tg && ++spins < (1u << 18));
    }
    __syncthreads();
}

// ---------------- prep kernels ----------------
__global__ void k_reset() {
    int i = blockIdx.x * blockDim.x + threadIdx.x;
    if (i < NB * 32) d_flags[i] = 0u;
    if (i < 2 * BB * H) {
        (&d_h0[0][0])[i] = 0.f;
        (&d_h1[0][0])[i] = 0.f;
    }
}

__global__ void k_pre(const float* __restrict__ Wih0, const float* __restrict__ cond,
                      const float* __restrict__ emb,
                      const float* __restrict__ bih0, const float* __restrict__ bhh0,
                      const float* __restrict__ bih1, const float* __restrict__ bhh1) {
    int i = blockIdx.x * blockDim.x + threadIdx.x;
    if (i < BB * G4) {                 // condW0
        int b = i >> 12, j = i & 4095;
        const float* wr = Wih0 + (size_t)j * 1152;
        const float* cb = cond + b * H;
        float s = bih0[j] + bhh0[j];
#pragma unroll 4
        for (int k = 0; k < H; ++k) s += wr[k] * cb[k];
        d_condW0[i] = s;
    }
    int i2 = i - BB * G4;
    if (i2 >= 0 && i2 < CLS * G4) {    // embproj
        int c = i2 >> 12, j = i2 & 4095;
        const float* wr = Wih0 + (size_t)j * 1152 + H;
        const float* eb = emb + c * EMBD;
        float s = 0.f;
#pragma unroll 4
        for (int k = 0; k < EMBD; ++k) s += wr[k] * eb[k];
        d_embproj[i2] = s;
    }
    int i3 = i - (BB + CLS) * G4;
    if (i3 >= 0 && i3 < G4) d_bias1[i3] = bih1[i3] + bhh1[i3];
}

// ---------------- persistent recurrent kernel ----------------
// L0 block bk<NBL0: elements e = bk*24+j (j<24); SMEM slot s = j*4+g -> Whh0[g*1024+e]
// L1 block: elements e = lb*12+j (j<12); slots [0,48): Wih1 (input h0[s], warps 0-3),
//                                        slots [48,96): Whh1 (input h1[s-1], warps 4-7)
// Pipeline: L0 computes h0[s] (needs f0>=s, f1>=s-1); L1 computes h1[s]
// (needs f0>=s+1, f1>=s). Double-buffered h keeps writer/reader steps disjoint.
__global__ void __launch_bounds__(256, 1)
k_recur(const long long* __restrict__ ids,
        const float* __restrict__ Whh0,
        const float* __restrict__ Wih1,
        const float* __restrict__ Whh1) {
    extern __shared__ char smem[];
    __half* sw = (__half*)smem;
    float (*gres)[2] = (float(*)[2])(smem + SMEM_W_BYTES);

    const int tid = threadIdx.x, bk = blockIdx.x;
    const int lane = tid & 31, warp = tid >> 5;
    const bool isL1 = (bk >= NBL0);
    const int lb = isL1 ? (bk - NBL0) : bk;
    const int ebase = isL1 ? lb * EL1 : lb * EL0;

    // ---- prologue: gather fp32 weight rows -> fp16 SMEM (once) ----
    for (int i = tid; i < RPB * 256; i += 256) {
        int s = i >> 8, c = i & 255;     // c = float4 index within the 1024-wide row
        int g, e; const float* src;
        if (!isL1)      { g = s & 3;        e = ebase + (s >> 2);        src = Whh0; }
        else if (s < 48){ g = s & 3;        e = ebase + (s >> 2);        src = Wih1; }
        else            { int s2 = s - 48; g = s2 & 3; e = ebase + (s2 >> 2); src = Whh1; }
        __half2 out0, out1;
        if (e < H) {
            float4 v = *(const float4*)(src + (size_t)(g * 1024 + e) * H + c * 4);
            out0 = __floats2half2_rn(v.x, v.y);
            out1 = __floats2half2_rn(v.z, v.w);
        } else {
            out0 = __floats2half2_rn(0.f, 0.f); out1 = out0;
        }
        uint2 packed;
        packed.x = *reinterpret_cast<unsigned*>(&out0);
        packed.y = *reinterpret_cast<unsigned*>(&out1);
        *(uint2*)(sw + (size_t)s * H + c * 4) = packed;
    }

    // ---- elementwise task setup (thread tid handles (j = tid/2, batch = tid&1)) ----
    const int nel = isL1 ? EL1 : EL0;
    const int jt = tid >> 1, bt = tid & 1;
    const int et = ebase + jt;
    const bool task = (jt < nel) && (et < H);
    float cw0 = 0, cw1 = 0, cw2 = 0, cw3 = 0;
    if (task) {
        if (!isL1) {
            const float* cw = d_condW0 + bt * G4 + et;
            cw0 = cw[0]; cw1 = cw[1024]; cw2 = cw[2048]; cw3 = cw[3072];
        } else {
            cw0 = d_bias1[et];        cw1 = d_bias1[et + 1024];
            cw2 = d_bias1[et + 2048]; cw3 = d_bias1[et + 3072];
        }
    }
    float cst = 0.f;   // cell state, register-resident for the whole sequence
    __syncthreads();   // SMEM weights ready

    unsigned long long hA[16], hB[16];   // lane's k-slice, packed f32x2 pairs

    for (int s = 0; s < TSTEPS; ++s) {
        // per-step elementwise prefetch (token projection, L0 only) — before the wait
        float ep0 = 0, ep1 = 0, ep2 = 0, ep3 = 0;
        if (task && !isL1) {
            int tok = (int)ids[bt * SEQ + s];
            const float* ep = d_embproj + tok * G4 + et;
            ep0 = ep[0]; ep1 = ep[1024]; ep2 = ep[2048]; ep3 = ep[3072];
        }

        // decoupled waits (slack on the cross-group flag absorbs jitter)
        if (!isL1) wait2(s,     s - 1, tid);
        else       wait2(s + 1, s,     tid);

        // h source per warp (single source per warp)
        const float* h0p = d_h0[(s + 1) & 1];   // h0[s-1]
        const float* h0c = d_h0[s & 1];          // h0[s]
        const float* h1p = d_h1[(s + 1) & 1];   // h1[s-1]
        const float* hsrc = !isL1 ? h0p : ((warp < 4) ? h0c : h1p);

        // refresh h slice: k = q*256 + lane*8 + j
#pragma unroll
        for (int q = 0; q < 4; ++q) {
            int kb = q * 256 + lane * 8;
            float4 a0 = *(const float4*)(hsrc + kb);
            float4 a1 = *(const float4*)(hsrc + kb + 4);
            hA[q*4+0] = pk(a0.x, a0.y); hA[q*4+1] = pk(a0.z, a0.w);
            hA[q*4+2] = pk(a1.x, a1.y); hA[q*4+3] = pk(a1.z, a1.w);
            float4 b0 = *(const float4*)(hsrc + H + kb);
            float4 b1 = *(const float4*)(hsrc + H + kb + 4);
            hB[q*4+0] = pk(b0.x, b0.y); hB[q*4+1] = pk(b0.z, b0.w);
            hB[q*4+2] = pk(b1.x, b1.y); hB[q*4+3] = pk(b1.z, b1.w);
        }

        // dot phase: 12 rows per warp, processed in pairs for ILP
#pragma unroll 2
        for (int rp = 0; rp < 6; ++rp) {
            const int s0 = warp * 12 + rp * 2;
            const uint4* w0 = (const uint4*)(sw + (size_t)s0 * H);
            const uint4* w1 = (const uint4*)(sw + (size_t)(s0 + 1) * H);
            unsigned long long aA0 = 0, aB0 = 0, aA1 = 0, aB1 = 0;
#pragma unroll
            for (int q = 0; q < 4; ++q) {
                uint4 u0 = w0[q * 32 + lane];
                uint4 u1 = w1[q * 32 + lane];
#pragma unroll
                for (int p = 0; p < 4; ++p) {
                    unsigned c0 = (&u0.x)[p], c1 = (&u1.x)[p];
                    float2 f0 = __half22float2(*reinterpret_cast<__half2*>(&c0));
                    float2 f1 = __half22float2(*reinterpret_cast<__half2*>(&c1));
                    unsigned long long wp0 = pk(f0.x, f0.y);
                    unsigned long long wp1 = pk(f1.x, f1.y);
                    fma2(aA0, wp0, hA[q*4+p]); fma2(aB0, wp0, hB[q*4+p]);
                    fma2(aA1, wp1, hA[q*4+p]); fma2(aB1, wp1, hB[q*4+p]);
                }
            }
            float2 xA0 = upk(aA0), xB0 = upk(aB0), xA1 = upk(aA1), xB1 = upk(aB1);
            float v0 = xA0.x + xA0.y, v1 = xB0.x + xB0.y;
            float v2 = xA1.x + xA1.y, v3 = xB1.x + xB1.y;
#pragma unroll
            for (int off = 16; off > 0; off >>= 1) {
                v0 += __shfl_xor_sync(0xffffffffu, v0, off);
                v1 += __shfl_xor_sync(0xffffffffu, v1, off);
                v2 += __shfl_xor_sync(0xffffffffu, v2, off);
                v3 += __shfl_xor_sync(0xffffffffu, v3, off);
            }
            if (lane == 0) {
                gres[s0][0] = v0;     gres[s0][1] = v1;
                gres[s0 + 1][0] = v2; gres[s0 + 1][1] = v3;
            }
        }
        __syncthreads();   // gres visible block-wide

        // elementwise phase (block-local gate gather)
        if (task) {
            const int j4 = jt * 4;
            float gi, gf, gg, go;
            if (!isL1) {
                gi = gres[j4 + 0][bt] + cw0 + ep0;
                gf = gres[j4 + 1][bt] + cw1 + ep1;
                gg = gres[j4 + 2][bt] + cw2 + ep2;
                go = gres[j4 + 3][bt] + cw3 + ep3;
            } else {
                gi = gres[j4 + 0][bt] + gres[48 + j4 + 0][bt] + cw0;
                gf = gres[j4 + 1][bt] + gres[48 + j4 + 1][bt] + cw1;
                gg = gres[j4 + 2][bt] + gres[48 + j4 + 2][bt] + cw2;
                go = gres[j4 + 3][bt] + gres[48 + j4 + 3][bt] + cw3;
            }
            cst = sigap(gf) * cst + sigap(gi) * tanhap(gg);
            float h = sigap(go) * tanhap(cst);
            if (!isL1) {
                d_h0[s & 1][bt * H + et] = h;
            } else {
                d_h1[s & 1][bt * H + et] = h;
                d_h1hist[(size_t)s * (BB * H) + bt * H + et] = h;
            }
        }
        __syncthreads();   // all h writes done before publish; also protects gres

        if (tid == 0) {
            asm volatile("st.release.gpu.u32 [%0], %1;"
                         :: "l"(d_flags + bk * 32), "r"((unsigned)(s + 1)) : "memory");
        }
    }
}

// ---------------- CE kernels ----------------
__global__ void k_ce(const long long* __restrict__ ids,
                     const float* __restrict__ fcw, const float* __restrict__ fcb) {
    __shared__ float hs[H];
    __shared__ float lg[32];
    const int m = blockIdx.x;           // 0..2045
    const int b = m & 1, t = m >> 1;
    const int tid = threadIdx.x, lane = tid & 31, warp = tid >> 5;

    const float* hp = d_h1hist + (size_t)t * BB * H + b * H;
    for (int i = tid; i < H; i += 256) hs[i] = hp[i];
    __syncthreads();

    for (int c = warp; c < CLS; c += 8) {
        const float* wr = fcw + c * H;
        float s = 0.f;
        for (int k = lane; k < H; k += 32) s += wr[k] * hs[k];
#pragma unroll
        for (int off = 16; off > 0; off >>= 1) s += __shfl_xor_sync(0xffffffffu, s, off);
        if (lane == 0) lg[c] = s + fcb[c];
    }
    __syncthreads();

    if (tid == 0) {
        float mx = -1e30f;
        for (int c = 0; c < CLS; ++c) mx = fmaxf(mx, lg[c]);
        float se = 0.f;
        for (int c = 0; c < CLS; ++c) se += expf(lg[c] - mx);
        float lse = mx + logf(se);
        int tgt = (int)ids[b * SEQ + t + 1];
        d_nll[m] = lse - lg[tgt];
    }
}

__global__ void k_loss(const float* __restrict__ mask, float* __restrict__ out) {
    __shared__ float s1s[256], s2s[256];
    const int tid = threadIdx.x;
    float sn = 0.f, sm = 0.f;
    for (int i = tid; i < TSTEPS * BB; i += 256) sn += d_nll[i];
    for (int i = tid; i < BB * TSTEPS; i += 256) {
        int b = i / TSTEPS, t = i % TSTEPS;
        sm += mask[b * SEQ + t + 1];
    }
    s1s[tid] = sn; s2s[tid] = sm;
    __syncthreads();
    for (int o = 128; o > 0; o >>= 1) {
        if (tid < o) { s1s[tid] += s1s[tid + o]; s2s[tid] += s2s[tid + o]; }
        __syncthreads();
    }
    if (tid == 0) {
        float ce = s1s[0] / (float)(TSTEPS * BB);
        float masked = ce * s2s[0] / s2s[0];   // matches reference (incl. mask==0 -> NaN)
        out[0] = ce + masked;
    }
}

// ---------------- launch ----------------
extern "C" void kernel_launch(void* const* d_in, const int* in_sizes, int n_in,
                              void* d_out, int out_size) {
    const long long* ids  = (const long long*)d_in[0];
    const float* mask     = (const float*)d_in[1];
    const float* cond     = (const float*)d_in[2];
    const float* emb      = (const float*)d_in[3];
    const float* Wih0     = (const float*)d_in[4];
    const float* Whh0     = (const float*)d_in[5];
    const float* bih0     = (const float*)d_in[6];
    const float* bhh0     = (const float*)d_in[7];
    const float* Wih1     = (const float*)d_in[8];
    const float* Whh1     = (const float*)d_in[9];
    const float* bih1     = (const float*)d_in[10];
    const float* bhh1     = (const float*)d_in[11];
    const float* fcw      = (const float*)d_in[12];
    const float* fcb      = (const float*)d_in[13];

    static bool init = false;
    if (!init) {
        cudaFuncSetAttribute(k_recur, cudaFuncAttributeMaxDynamicSharedMemorySize,
                             (int)SMEM_TOTAL);
        init = true;
    }

    k_reset<<<32, 256>>>();
    k_pre<<<((BB + CLS + 1) * G4 + 255) / 256, 256>>>(Wih0, cond, emb, bih0, bhh0, bih1, bhh1);
    k_recur<<<NB, 256, SMEM_TOTAL>>>(ids, Whh0, Wih1, Whh1);
    k_ce<<<TSTEPS * BB, 256>>>(ids, fcw, fcb);
    k_loss<<<1, 256>>>(mask, (float*)d_out);
}

// round 8
// speedup vs baseline: 2.2023x; 1.3552x over previous
#include <cuda_runtime.h>
#include <cuda_fp16.h>

// Problem constants
#define H      1024
#define BB     2
#define CLS    30
#define EMBD   128
#define SEQ    1024
#define TSTEPS 1023      // n_seq - 1
#define G4     4096      // 4*H gate rows per layer

// Block partition: gate rows of an element live in ONE block.
#define NBL0   43        // L0 blocks: 24 elements x 4 gate rows = 96 rows
#define EL0    24
#define NBL1   86        // L1 blocks: 12 elements x 8 rows (4 Wih1 + 4 Whh1) = 96
#define EL1    12
#define NB     (NBL0 + NBL1)   // 129 blocks, one per SM, co-resident
#define RPB    96

// SMEM layout: padded weight rows (conflict-free ldmatrix), h staging, gate results
#define RS     1032                    // halves per weight row (1024 + 8 pad)
#define RSB    (RS * 2)                // 2064 bytes
#define SWB    ((size_t)RPB * RSB)     // 198144 bytes of weights
#define HSB    (4 * RSB)               // 4 padded h rows (8256 bytes)
#define SMEM_TOTAL (SWB + HSB + RPB * 2 * sizeof(float))   // + gres = 207168

// ---------------- persistent device state ----------------
__device__ float    d_condW0[BB * G4];                   // cond @ Wih0[:, :H]^T + b_ih0 + b_hh0
__device__ float    d_embproj[CLS * G4];                 // emb  @ Wih0[:, H:]^T per class
__device__ float    d_bias1[G4];                         // b_ih1 + b_hh1
__device__ __half   d_h0f16[2][BB * H];                  // double-buffered fp16 h0
__device__ __half   d_h1f16[2][BB * H];                  // double-buffered fp16 h1
__device__ float    d_h1hist[(size_t)TSTEPS * BB * H];   // layer-1 outputs (fp32) for CE
__device__ unsigned d_flags[NB * 32];                    // per-block monotonic progress flags
__device__ float    d_nll[TSTEPS * BB];

// ---------------- helpers ----------------
__device__ __forceinline__ float tanhap(float x) {
    float y; asm("tanh.approx.f32 %0, %1;" : "=f"(y) : "f"(x)); return y;
}
__device__ __forceinline__ float sigap(float x) { return 0.5f * tanhap(0.5f * x) + 0.5f; }

// Decoupled wait: threads [0,NBL0) poll L0 flags against tgt0; threads
// [64, 64+NBL1) poll L1 flags against tgt1. Bounded spin: a sync bug degrades
// to a wrong answer + diagnostics instead of a container-killing hang.
__device__ __forceinline__ void wait2(int tgt0, int tgt1, int tid) {
    int fi = -1, tg = 0;
    if (tid < NBL0)                        { fi = tid;               tg = tgt0; }
    else if (tid >= 64 && tid < 64 + NBL1) { fi = NBL0 + (tid - 64); tg = tgt1; }
    if (fi >= 0 && tg > 0) {
        const unsigned* p = d_flags + fi * 32;
        unsigned v; unsigned spins = 0;
        do {
            asm volatile("ld.acquire.gpu.u32 %0, [%1];" : "=r"(v) : "l"(p) : "memory");
        } while ((int)v < tg && ++spins < (1u << 18));
    }
    __syncthreads();
}

// ---------------- prep kernels ----------------
__global__ void k_reset() {
    int i = blockIdx.x * blockDim.x + threadIdx.x;
    if (i < NB * 32) d_flags[i] = 0u;
    if (i < 2 * BB * H) {
        ((__half*)d_h0f16)[i] = __float2half(0.f);
        ((__half*)d_h1f16)[i] = __float2half(0.f);
    }
}

__global__ void k_pre(const float* __restrict__ Wih0, const float* __restrict__ cond,
                      const float* __restrict__ emb,
                      const float* __restrict__ bih0, const float* __restrict__ bhh0,
                      const float* __restrict__ bih1, const float* __restrict__ bhh1) {
    int i = blockIdx.x * blockDim.x + threadIdx.x;
    if (i < BB * G4) {                 // condW0
        int b = i >> 12, j = i & 4095;
        const float* wr = Wih0 + (size_t)j * 1152;
        const float* cb = cond + b * H;
        float s = bih0[j] + bhh0[j];
#pragma unroll 4
        for (int k = 0; k < H; ++k) s += wr[k] * cb[k];
        d_condW0[i] = s;
    }
    int i2 = i - BB * G4;
    if (i2 >= 0 && i2 < CLS * G4) {    // embproj
        int c = i2 >> 12, j = i2 & 4095;
        const float* wr = Wih0 + (size_t)j * 1152 + H;
        const float* eb = emb + c * EMBD;
        float s = 0.f;
#pragma unroll 4
        for (int k = 0; k < EMBD; ++k) s += wr[k] * eb[k];
        d_embproj[i2] = s;
    }
    int i3 = i - (BB + CLS) * G4;
    if (i3 >= 0 && i3 < G4) d_bias1[i3] = bih1[i3] + bhh1[i3];
}

// ---------------- persistent recurrent kernel ----------------
// L0 block bk<NBL0: elements e = bk*24+j; weight slot s = j*4+g -> Whh0[g*1024+e]
// L1 block: elements e = lb*12+j; slots [0,48): Wih1 (input h0[s]),
//                                 slots [48,96): Whh1 (input h1[s-1])
// Dot phase = D[96x2] = W[96x1024] * h[1024x2] via mma.sync m16n8k16 (fp32 acc):
//   warp w<6 owns rows [16w,16w+16); 64 k-steps; A via ldmatrix.x4 from padded
//   SMEM rows; B built from fp16 h staged in SMEM (lanes with n>=2 contribute 0).
// Pipeline: L0@s needs f0>=s, f1>=s-1; L1@s needs f0>=s+1, f1>=s (1-step slack).
__global__ void __launch_bounds__(256, 1)
k_recur(const long long* __restrict__ ids,
        const float* __restrict__ Whh0,
        const float* __restrict__ Wih1,
        const float* __restrict__ Whh1) {
    extern __shared__ char smem[];
    __half* sw  = (__half*)smem;
    __half* hsm = (__half*)(smem + SWB);
    float (*gres)[2] = (float(*)[2])(smem + SWB + HSB);
    const unsigned smem_u32 = (unsigned)__cvta_generic_to_shared(smem);
    const unsigned hsm_u32  = smem_u32 + (unsigned)SWB;

    const int tid = threadIdx.x, bk = blockIdx.x;
    const int lane = tid & 31, warp = tid >> 5;
    const bool isL1 = (bk >= NBL0);
    const int lb = isL1 ? (bk - NBL0) : bk;
    const int ebase = isL1 ? lb * EL1 : lb * EL0;

    // ---- prologue: gather fp32 weight rows -> fp16 SMEM, padded stride (once) ----
    for (int i = tid; i < RPB * 256; i += 256) {
        int s = i >> 8, c = i & 255;     // c = float4 index within the 1024-wide row
        int g, e; const float* src;
        if (!isL1)      { g = s & 3;        e = ebase + (s >> 2);        src = Whh0; }
        else if (s < 48){ g = s & 3;        e = ebase + (s >> 2);        src = Wih1; }
        else            { int s2 = s - 48; g = s2 & 3; e = ebase + (s2 >> 2); src = Whh1; }
        __half2 out0, out1;
        if (e < H) {
            float4 v = *(const float4*)(src + (size_t)(g * 1024 + e) * H + c * 4);
            out0 = __floats2half2_rn(v.x, v.y);
            out1 = __floats2half2_rn(v.z, v.w);
        } else {
            out0 = __floats2half2_rn(0.f, 0.f); out1 = out0;
        }
        uint2 packed;
        packed.x = *reinterpret_cast<unsigned*>(&out0);
        packed.y = *reinterpret_cast<unsigned*>(&out1);
        *(uint2*)(sw + (size_t)s * RS + c * 4) = packed;
    }

    // ---- elementwise task setup (thread tid -> (j = tid/2, batch = tid&1)) ----
    const int nel = isL1 ? EL1 : EL0;
    const int jt = tid >> 1, bt = tid & 1;
    const int et = ebase + jt;
    const bool task = (jt < nel) && (et < H);
    float cw0 = 0, cw1 = 0, cw2 = 0, cw3 = 0;
    if (task) {
        if (!isL1) {
            const float* cw = d_condW0 + bt * G4 + et;
            cw0 = cw[0]; cw1 = cw[1024]; cw2 = cw[2048]; cw3 = cw[3072];
        } else {
            cw0 = d_bias1[et];        cw1 = d_bias1[et + 1024];
            cw2 = d_bias1[et + 2048]; cw3 = d_bias1[et + 3072];
        }
    }
    float cst = 0.f;   // cell state, register-resident for the whole sequence

    // ---- mma operand addressing (constant across steps except h row base) ----
    const bool mmaw = (warp < 6);
    const int arow = lane & 15;
    const unsigned a_addr0 = smem_u32 + (unsigned)((warp * 16 + arow) * RSB + ((lane >> 4) * 16));
    const int nidx = lane >> 2;
    const bool nreal = (nidx < 2);
    const int hrowbase = (isL1 && warp >= 3) ? 2 : 0;   // L1 warps 3-5 read h1p rows
    const unsigned b_addr0 = hsm_u32 + (unsigned)((hrowbase + (nreal ? nidx : 0)) * RSB
                                                  + (lane & 3) * 4);
    __syncthreads();   // SMEM weights ready

    for (int s = 0; s < TSTEPS; ++s) {
        // per-step elementwise prefetch (token projection, L0 only) — before the wait
        float ep0 = 0, ep1 = 0, ep2 = 0, ep3 = 0;
        if (task && !isL1) {
            int tok = (int)ids[bt * SEQ + s];
            const float* ep = d_embproj + tok * G4 + et;
            ep0 = ep[0]; ep1 = ep[1024]; ep2 = ep[2048]; ep3 = ep[3072];
        }

        // decoupled waits (slack on the cross-group flag absorbs jitter)
        if (!isL1) wait2(s,     s - 1, tid);
        else       wait2(s + 1, s,     tid);

        // stage fp16 h into padded SMEM rows
        {
            int idx = tid * 8;                     // 8 halves per thread
            int row = idx >> 10, col = idx & 1023;
            if (!isL1) {                            // rows 0-1 <- h0[s-1]
                const __half* src = d_h0f16[(s + 1) & 1];
                *(uint4*)(hsm + row * RS + col) = *(const uint4*)(src + idx);
            } else {                                // rows 0-1 <- h0[s]; rows 2-3 <- h1[s-1]
                const __half* s0 = d_h0f16[s & 1];
                const __half* s1 = d_h1f16[(s + 1) & 1];
                *(uint4*)(hsm + row * RS + col)            = *(const uint4*)(s0 + idx);
                *(uint4*)(hsm + (2 + row) * RS + col)      = *(const uint4*)(s1 + idx);
            }
        }
        __syncthreads();   // h staged

        // ---- dot phase: mma.sync, 16 rows per warp, 4 accumulator chains ----
        if (mmaw) {
            float d0[4] = {0,0,0,0}, d1[4] = {0,0,0,0};
            float d2[4] = {0,0,0,0}, d3[4] = {0,0,0,0};
#pragma unroll
            for (int ks = 0; ks < 64; ++ks) {
                unsigned a0, a1, a2, a3;
                asm volatile("ldmatrix.sync.aligned.m8n8.x4.shared.b16 {%0,%1,%2,%3}, [%4];"
                             : "=r"(a0), "=r"(a1), "=r"(a2), "=r"(a3)
                             : "r"(a_addr0 + ks * 32));
                unsigned b0 = 0, b1 = 0;
                if (nreal) {
                    asm volatile("ld.shared.u32 %0, [%1];" : "=r"(b0) : "r"(b_addr0 + ks * 32));
                    asm volatile("ld.shared.u32 %0, [%1];" : "=r"(b1) : "r"(b_addr0 + ks * 32 + 16));
                }
                const int ch = ks & 3;
                asm volatile("mma.sync.aligned.m16n8k16.row.col.f32.f16.f16.f32 "
                             "{%0,%1,%2,%3}, {%4,%5,%6,%7}, {%8,%9}, {%0,%1,%2,%3};"
                             : "+f"(d0[ch]), "+f"(d1[ch]), "+f"(d2[ch]), "+f"(d3[ch])
                             : "r"(a0), "r"(a1), "r"(a2), "r"(a3), "r"(b0), "r"(b1));
            }
            if ((lane & 3) == 0) {
                const int g = lane >> 2;
                const int r = warp * 16 + g;
                float2 lo = make_float2(d0[0] + d0[1] + d0[2] + d0[3],
                                        d1[0] + d1[1] + d1[2] + d1[3]);
                float2 hi = make_float2(d2[0] + d2[1] + d2[2] + d2[3],
                                        d3[0] + d3[1] + d3[2] + d3[3]);
                *(float2*)&gres[r][0]     = lo;   // rows r   : batch 0,1
                *(float2*)&gres[r + 8][0] = hi;   // rows r+8 : batch 0,1
            }
        }
        __syncthreads();   // gres visible block-wide

        // ---- elementwise phase (block-local gate gather) ----
        if (task) {
            const int j4 = jt * 4;
            float gi, gf, gg, go;
            if (!isL1) {
                gi = gres[j4 + 0][bt] + cw0 + ep0;
                gf = gres[j4 + 1][bt] + cw1 + ep1;
                gg = gres[j4 + 2][bt] + cw2 + ep2;
                go = gres[j4 + 3][bt] + cw3 + ep3;
            } else {
                gi = gres[j4 + 0][bt] + gres[48 + j4 + 0][bt] + cw0;
                gf = gres[j4 + 1][bt] + gres[48 + j4 + 1][bt] + cw1;
                gg = gres[j4 + 2][bt] + gres[48 + j4 + 2][bt] + cw2;
                go = gres[j4 + 3][bt] + gres[48 + j4 + 3][bt] + cw3;
            }
            cst = sigap(gf) * cst + sigap(gi) * tanhap(gg);
            float h = sigap(go) * tanhap(cst);
            if (!isL1) {
                d_h0f16[s & 1][bt * H + et] = __float2half(h);
            } else {
                d_h1f16[s & 1][bt * H + et] = __float2half(h);
                d_h1hist[(size_t)s * (BB * H) + bt * H + et] = h;
            }
        }
        __syncthreads();   // all h writes done before publish; also protects gres/hsm

        if (tid == 0) {
            asm volatile("st.release.gpu.u32 [%0], %1;"
                         :: "l"(d_flags + bk * 32), "r"((unsigned)(s + 1)) : "memory");
        }
    }
}

// ---------------- CE kernels ----------------
__global__ void k_ce(const long long* __restrict__ ids,
                     const float* __restrict__ fcw, const float* __restrict__ fcb) {
    __shared__ float hs[H];
    __shared__ float lg[32];
    const int m = blockIdx.x;           // 0..2045
    const int b = m & 1, t = m >> 1;
    const int tid = threadIdx.x, lane = tid & 31, warp = tid >> 5;

    const float* hp = d_h1hist + (size_t)t * BB * H + b * H;
    for (int i = tid; i < H; i += 256) hs[i] = hp[i];
    __syncthreads();

    for (int c = warp; c < CLS; c += 8) {
        const float* wr = fcw + c * H;
        float s = 0.f;
        for (int k = lane; k < H; k += 32) s += wr[k] * hs[k];
#pragma unroll
        for (int off = 16; off > 0; off >>= 1) s += __shfl_xor_sync(0xffffffffu, s, off);
        if (lane == 0) lg[c] = s + fcb[c];
    }
    __syncthreads();

    if (tid == 0) {
        float mx = -1e30f;
        for (int c = 0; c < CLS; ++c) mx = fmaxf(mx, lg[c]);
        float se = 0.f;
        for (int c = 0; c < CLS; ++c) se += expf(lg[c] - mx);
        float lse = mx + logf(se);
        int tgt = (int)ids[b * SEQ + t + 1];
        d_nll[m] = lse - lg[tgt];
    }
}

__global__ void k_loss(const float* __restrict__ mask, float* __restrict__ out) {
    __shared__ float s1s[256], s2s[256];
    const int tid = threadIdx.x;
    float sn = 0.f, sm = 0.f;
    for (int i = tid; i < TSTEPS * BB; i += 256) sn += d_nll[i];
    for (int i = tid; i < BB * TSTEPS; i += 256) {
        int b = i / TSTEPS, t = i % TSTEPS;
        sm += mask[b * SEQ + t + 1];
    }
    s1s[tid] = sn; s2s[tid] = sm;
    __syncthreads();
    for (int o = 128; o > 0; o >>= 1) {
        if (tid < o) { s1s[tid] += s1s[tid + o]; s2s[tid] += s2s[tid + o]; }
        __syncthreads();
    }
    if (tid == 0) {
        float ce = s1s[0] / (float)(TSTEPS * BB);
        float masked = ce * s2s[0] / s2s[0];   // matches reference (incl. mask==0 -> NaN)
        out[0] = ce + masked;
    }
}

// ---------------- launch ----------------
extern "C" void kernel_launch(void* const* d_in, const int* in_sizes, int n_in,
                              void* d_out, int out_size) {
    const long long* ids  = (const long long*)d_in[0];
    const float* mask     = (const float*)d_in[1];
    const float* cond     = (const float*)d_in[2];
    const float* emb      = (const float*)d_in[3];
    const float* Wih0     = (const float*)d_in[4];
    const float* Whh0     = (const float*)d_in[5];
    const float* bih0     = (const float*)d_in[6];
    const float* bhh0     = (const float*)d_in[7];
    const float* Wih1     = (const float*)d_in[8];
    const float* Whh1     = (const float*)d_in[9];
    const float* bih1     = (const float*)d_in[10];
    const float* bhh1     = (const float*)d_in[11];
    const float* fcw      = (const float*)d_in[12];
    const float* fcb      = (const float*)d_in[13];

    static bool init = false;
    if (!init) {
        cudaFuncSetAttribute(k_recur, cudaFuncAttributeMaxDynamicSharedMemorySize,
                             (int)SMEM_TOTAL);
        init = true;
    }

    k_reset<<<32, 256>>>();
    k_pre<<<((BB + CLS + 1) * G4 + 255) / 256, 256>>>(Wih0, cond, emb, bih0, bhh0, bih1, bhh1);
    k_recur<<<NB, 256, SMEM_TOTAL>>>(ids, Whh0, Wih1, Whh1);
    k_ce<<<TSTEPS * BB, 256>>>(ids, fcw, fcb);
    k_loss<<<1, 256>>>(mask, (float*)d_out);
}

// round 10
// speedup vs baseline: 2.6469x; 1.2019x over previous
#include <cuda_runtime.h>
#include <cuda_fp16.h>

// Problem constants
#define H      1024
#define BB     2
#define CLS    30
#define EMBD   128
#define SEQ    1024
#define TSTEPS 1023      // n_seq - 1
#define G4     4096      // 4*H gate rows per layer

// Block partition: gate rows of an element live in ONE block.
#define NBL0   43        // L0 blocks: 24 elements x 4 gate rows = 96 rows
#define EL0    24
#define NBL1   86        // L1 blocks: 12 elements x 8 rows (4 Wih1 + 4 Whh1) = 96
#define EL1    12
#define NB     (NBL0 + NBL1)   // 129 blocks, one per SM, co-resident
#define RPB    96

// SMEM layout: padded weight rows (conflict-free ldmatrix), h staging, gate results
#define RS     1032                    // halves per weight row (1024 + 8 pad)
#define RSB    (RS * 2)                // 2064 bytes
#define SWB    ((size_t)RPB * RSB)     // 198144 bytes of weights
#define HSB    (4 * RSB)               // 4 padded h rows (8256 bytes)
#define SMEM_TOTAL (SWB + HSB + RPB * 2 * sizeof(float))   // + gres = 207168

// ---------------- persistent device state ----------------
__device__ float    d_condW0[BB * G4];                   // cond @ Wih0[:, :H]^T + b_ih0 + b_hh0
__device__ float    d_embproj[CLS * G4];                 // emb  @ Wih0[:, H:]^T per class
__device__ float    d_bias1[G4];                         // b_ih1 + b_hh1
__device__ __half   d_h0f16[2][BB * H];                  // double-buffered fp16 h0
__device__ __half   d_h1f16[2][BB * H];                  // double-buffered fp16 h1
__device__ float    d_h1hist[(size_t)TSTEPS * BB * H];   // layer-1 outputs (fp32) for CE
__device__ unsigned d_ctr[64];                           // [0]=L0 epoch counter, [32]=L1
__device__ float    d_nll[TSTEPS * BB];

// ---------------- helpers ----------------
__device__ __forceinline__ float tanhap(float x) {
    float y; asm("tanh.approx.f32 %0, %1;" : "=f"(y) : "f"(x)); return y;
}
__device__ __forceinline__ float sigap(float x) { return 0.5f * tanhap(0.5f * x) + 0.5f; }

// Aggregated-epoch wait: thread 0 polls the L0 counter, thread 32 polls the L1
// counter (2 pollers per block instead of ~130). Spin bound 2^16: even with a
// total sync failure a launch finishes in ~2 s (wrong answer + diagnostics),
// never a container-killing hang; the normal path exits in < 1e3 polls.
__device__ __forceinline__ void waitc(int t0, int t1, int tid) {
    if (tid == 0 && t0 > 0) {
        const unsigned* p = &d_ctr[0];
        unsigned v; unsigned spins = 0;
        do {
            asm volatile("ld.acquire.gpu.u32 %0, [%1];" : "=r"(v) : "l"(p) : "memory");
        } while ((int)v < t0 && ++spins < (1u << 16));
    } else if (tid == 32 && t1 > 0) {
        const unsigned* p = &d_ctr[32];
        unsigned v; unsigned spins = 0;
        do {
            asm volatile("ld.acquire.gpu.u32 %0, [%1];" : "=r"(v) : "l"(p) : "memory");
        } while ((int)v < t1 && ++spins < (1u << 16));
    }
    __syncthreads();
}

// ---------------- prep kernels ----------------
__global__ void k_reset() {
    int i = blockIdx.x * blockDim.x + threadIdx.x;
    if (i < 64) d_ctr[i] = 0u;
    if (i < 2 * BB * H) {
        ((__half*)d_h0f16)[i] = __float2half(0.f);
        ((__half*)d_h1f16)[i] = __float2half(0.f);
    }
}

__global__ void k_pre(const float* __restrict__ Wih0, const float* __restrict__ cond,
                      const float* __restrict__ emb,
                      const float* __restrict__ bih0, const float* __restrict__ bhh0,
                      const float* __restrict__ bih1, const float* __restrict__ bhh1) {
    int i = blockIdx.x * blockDim.x + threadIdx.x;
    if (i < BB * G4) {                 // condW0
        int b = i >> 12, j = i & 4095;
        const float* wr = Wih0 + (size_t)j * 1152;
        const float* cb = cond + b * H;
        float s = bih0[j] + bhh0[j];
#pragma unroll 4
        for (int k = 0; k < H; ++k) s += wr[k] * cb[k];
        d_condW0[i] = s;
    }
    int i2 = i - BB * G4;
    if (i2 >= 0 && i2 < CLS * G4) {    // embproj
        int c = i2 >> 12, j = i2 & 4095;
        const float* wr = Wih0 + (size_t)j * 1152 + H;
        const float* eb = emb + c * EMBD;
        float s = 0.f;
#pragma unroll 4
        for (int k = 0; k < EMBD; ++k) s += wr[k] * eb[k];
        d_embproj[i2] = s;
    }
    int i3 = i - (BB + CLS) * G4;
    if (i3 >= 0 && i3 < G4) d_bias1[i3] = bih1[i3] + bhh1[i3];
}

// ---------------- persistent recurrent kernel ----------------
// L0 block bk<NBL0: elements e = bk*24+j; weight slot s = j*4+g -> Whh0[g*1024+e]
// L1 block: elements e = lb*12+j; slots [0,48): Wih1 (input h0[s]),
//                                 slots [48,96): Whh1 (input h1[s-1])
// Dot phase = D[96x2] = W[96x1024] * h[1024x2] via mma.sync m16n8k16 (fp32 acc).
// A fragments for k-steps [0,32) are STEP-INVARIANT -> preloaded once into 128
// registers; k-steps [32,64) come via ldmatrix (halves per-step SMEM traffic).
// Pipeline epochs: L0@s needs ctr0>=43s, ctr1>=86(s-1);
//                  L1@s needs ctr0>=43(s+1), ctr1>=86s. (1-step slack, dbl-buffered h)
__global__ void __launch_bounds__(256, 1)
k_recur(const long long* __restrict__ ids,
        const float* __restrict__ Whh0,
        const float* __restrict__ Wih1,
        const float* __restrict__ Whh1) {
    extern __shared__ char smem[];
    __half* sw  = (__half*)smem;
    __half* hsm = (__half*)(smem + SWB);
    float (*gres)[2] = (float(*)[2])(smem + SWB + HSB);
    const unsigned smem_u32 = (unsigned)__cvta_generic_to_shared(smem);
    const unsigned hsm_u32  = smem_u32 + (unsigned)SWB;

    const int tid = threadIdx.x, bk = blockIdx.x;
    const int lane = tid & 31, warp = tid >> 5;
    const bool isL1 = (bk >= NBL0);
    const int lb = isL1 ? (bk - NBL0) : bk;
    const int ebase = isL1 ? lb * EL1 : lb * EL0;

    // ---- prologue: gather fp32 weight rows -> fp16 SMEM, padded stride (once) ----
    for (int i = tid; i < RPB * 256; i += 256) {
        int s = i >> 8, c = i & 255;     // c = float4 index within the 1024-wide row
        int g, e; const float* src;
        if (!isL1)      { g = s & 3;        e = ebase + (s >> 2);        src = Whh0; }
        else if (s < 48){ g = s & 3;        e = ebase + (s >> 2);        src = Wih1; }
        else            { int s2 = s - 48; g = s2 & 3; e = ebase + (s2 >> 2); src = Whh1; }
        __half2 out0, out1;
        if (e < H) {
            float4 v = *(const float4*)(src + (size_t)(g * 1024 + e) * H + c * 4);
            out0 = __floats2half2_rn(v.x, v.y);
            out1 = __floats2half2_rn(v.z, v.w);
        } else {
            out0 = __floats2half2_rn(0.f, 0.f); out1 = out0;
        }
        uint2 packed;
        packed.x = *reinterpret_cast<unsigned*>(&out0);
        packed.y = *reinterpret_cast<unsigned*>(&out1);
        *(uint2*)(sw + (size_t)s * RS + c * 4) = packed;
    }

    // ---- elementwise task setup (thread tid -> (j = tid/2, batch = tid&1)) ----
    const int nel = isL1 ? EL1 : EL0;
    const int jt = tid >> 1, bt = tid & 1;
    const int et = ebase + jt;
    const bool task = (jt < nel) && (et < H);
    float cw0 = 0, cw1 = 0, cw2 = 0, cw3 = 0;
    if (task) {
        if (!isL1) {
            const float* cw = d_condW0 + bt * G4 + et;
            cw0 = cw[0]; cw1 = cw[1024]; cw2 = cw[2048]; cw3 = cw[3072];
        } else {
            cw0 = d_bias1[et];        cw1 = d_bias1[et + 1024];
            cw2 = d_bias1[et + 2048]; cw3 = d_bias1[et + 3072];
        }
    }
    float cst = 0.f;   // cell state, register-resident for the whole sequence

    // ---- mma operand addressing (constant across steps) ----
    const bool mmaw = (warp < 6);
    const int arow = lane & 15;
    const unsigned a_addr0 = smem_u32 + (unsigned)((warp * 16 + arow) * RSB + ((lane >> 4) * 16));
    const int nidx = lane >> 2;
    const bool nreal = (nidx < 2);
    const int hrowbase = (isL1 && warp >= 3) ? 2 : 0;   // L1 warps 3-5 read h1p rows
    const unsigned b_addr0 = hsm_u32 + (unsigned)((hrowbase + (nreal ? nidx : 0)) * RSB
                                                  + (lane & 3) * 4);
    __syncthreads();   // SMEM weights ready

    // ---- preload step-invariant A fragments for k-steps [0,32) into registers ----
    unsigned ar0[32], ar1[32], ar2[32], ar3[32];
    if (mmaw) {
#pragma unroll
        for (int k = 0; k < 32; ++k) {
            asm volatile("ldmatrix.sync.aligned.m8n8.x4.shared.b16 {%0,%1,%2,%3}, [%4];"
                         : "=r"(ar0[k]), "=r"(ar1[k]), "=r"(ar2[k]), "=r"(ar3[k])
                         : "r"(a_addr0 + k * 32));
        }
    }

    const unsigned* ctr0p = &d_ctr[0];
    const unsigned* ctr1p = &d_ctr[32];

    for (int s = 0; s < TSTEPS; ++s) {
        // per-step elementwise prefetch (token projection, L0 only) — before the wait
        float ep0 = 0, ep1 = 0, ep2 = 0, ep3 = 0;
        if (task && !isL1) {
            int tok = (int)ids[bt * SEQ + s];
            const float* ep = d_embproj + tok * G4 + et;
            ep0 = ep[0]; ep1 = ep[1024]; ep2 = ep[2048]; ep3 = ep[3072];
        }

        // epoch waits (cross-group slack absorbs jitter)
        if (!isL1) waitc(NBL0 * s,       NBL1 * (s - 1), tid);
        else       waitc(NBL0 * (s + 1), NBL1 * s,       tid);

        // stage fp16 h into padded SMEM rows
        {
            int idx = tid * 8;                     // 8 halves per thread
            int row = idx >> 10, col = idx & 1023;
            if (!isL1) {                            // rows 0-1 <- h0[s-1]
                const __half* src = d_h0f16[(s + 1) & 1];
                *(uint4*)(hsm + row * RS + col) = *(const uint4*)(src + idx);
            } else {                                // rows 0-1 <- h0[s]; rows 2-3 <- h1[s-1]
                const __half* s0 = d_h0f16[s & 1];
                const __half* s1 = d_h1f16[(s + 1) & 1];
                *(uint4*)(hsm + row * RS + col)       = *(const uint4*)(s0 + idx);
                *(uint4*)(hsm + (2 + row) * RS + col) = *(const uint4*)(s1 + idx);
            }
        }
        __syncthreads();   // h staged

        // ---- dot phase: mma.sync, 16 rows per warp, 4 accumulator chains ----
        if (mmaw) {
            float d0[4] = {0,0,0,0}, d1[4] = {0,0,0,0};
            float d2[4] = {0,0,0,0}, d3[4] = {0,0,0,0};
            // SMEM half: k-steps [32,64) via ldmatrix
#pragma unroll
            for (int k = 0; k < 32; ++k) {
                unsigned a0, a1, a2, a3;
                asm volatile("ldmatrix.sync.aligned.m8n8.x4.shared.b16 {%0,%1,%2,%3}, [%4];"
                             : "=r"(a0), "=r"(a1), "=r"(a2), "=r"(a3)
                             : "r"(a_addr0 + (32 + k) * 32));
                unsigned b0 = 0, b1 = 0;
                if (nreal) {
                    asm volatile("ld.shared.u32 %0, [%1];" : "=r"(b0) : "r"(b_addr0 + (32 + k) * 32));
                    asm volatile("ld.shared.u32 %0, [%1];" : "=r"(b1) : "r"(b_addr0 + (32 + k) * 32 + 16));
                }
                const int ch = k & 3;
                asm volatile("mma.sync.aligned.m16n8k16.row.col.f32.f16.f16.f32 "
                             "{%0,%1,%2,%3}, {%4,%5,%6,%7}, {%8,%9}, {%0,%1,%2,%3};"
                             : "+f"(d0[ch]), "+f"(d1[ch]), "+f"(d2[ch]), "+f"(d3[ch])
                             : "r"(a0), "r"(a1), "r"(a2), "r"(a3), "r"(b0), "r"(b1));
            }
            // register half: k-steps [0,32), A already resident
#pragma unroll
            for (int k = 0; k < 32; ++k) {
                unsigned b0 = 0, b1 = 0;
                if (nreal) {
                    asm volatile("ld.shared.u32 %0, [%1];" : "=r"(b0) : "r"(b_addr0 + k * 32));
                    asm volatile("ld.shared.u32 %0, [%1];" : "=r"(b1) : "r"(b_addr0 + k * 32 + 16));
                }
                const int ch = k & 3;
                asm volatile("mma.sync.aligned.m16n8k16.row.col.f32.f16.f16.f32 "
                             "{%0,%1,%2,%3}, {%4,%5,%6,%7}, {%8,%9}, {%0,%1,%2,%3};"
                             : "+f"(d0[ch]), "+f"(d1[ch]), "+f"(d2[ch]), "+f"(d3[ch])
                             : "r"(ar0[k]), "r"(ar1[k]), "r"(ar2[k]), "r"(ar3[k]),
                               "r"(b0), "r"(b1));
            }
            if ((lane & 3) == 0) {
                const int g = lane >> 2;
                const int r = warp * 16 + g;
                float2 lo = make_float2(d0[0] + d0[1] + d0[2] + d0[3],
                                        d1[0] + d1[1] + d1[2] + d1[3]);
                float2 hi = make_float2(d2[0] + d2[1] + d2[2] + d2[3],
                                        d3[0] + d3[1] + d3[2] + d3[3]);
                *(float2*)&gres[r][0]     = lo;   // rows r   : batch 0,1
                *(float2*)&gres[r + 8][0] = hi;   // rows r+8 : batch 0,1
            }
        }
        __syncthreads();   // gres visible block-wide

        // ---- elementwise phase (block-local gate gather) ----
        if (task) {
            const int j4 = jt * 4;
            float gi, gf, gg, go;
            if (!isL1) {
                gi = gres[j4 + 0][bt] + cw0 + ep0;
                gf = gres[j4 + 1][bt] + cw1 + ep1;
                gg = gres[j4 + 2][bt] + cw2 + ep2;
                go = gres[j4 + 3][bt] + cw3 + ep3;
            } else {
                gi = gres[j4 + 0][bt] + gres[48 + j4 + 0][bt] + cw0;
                gf = gres[j4 + 1][bt] + gres[48 + j4 + 1][bt] + cw1;
                gg = gres[j4 + 2][bt] + gres[48 + j4 + 2][bt] + cw2;
                go = gres[j4 + 3][bt] + gres[48 + j4 + 3][bt] + cw3;
            }
            cst = sigap(gf) * cst + sigap(gi) * tanhap(gg);
            float h = sigap(go) * tanhap(cst);
            if (!isL1) {
                d_h0f16[s & 1][bt * H + et] = __float2half(h);
            } else {
                d_h1f16[s & 1][bt * H + et] = __float2half(h);
                d_h1hist[(size_t)s * (BB * H) + bt * H + et] = h;
            }
        }
        __syncthreads();   // all h writes done before publish; also protects gres/hsm

        if (tid == 0) {
            const unsigned* ctr = isL1 ? ctr1p : ctr0p;
            asm volatile("red.release.gpu.global.add.u32 [%0], %1;"
                         :: "l"(ctr), "r"(1u) : "memory");
        }
    }
}

// ---------------- CE kernels ----------------
__global__ void k_ce(const long long* __restrict__ ids,
                     const float* __restrict__ fcw, const float* __restrict__ fcb) {
    __shared__ float hs[H];
    __shared__ float lg[32];
    const int m = blockIdx.x;           // 0..2045
    const int b = m & 1, t = m >> 1;
    const int tid = threadIdx.x, lane = tid & 31, warp = tid >> 5;

    const float* hp = d_h1hist + (size_t)t * BB * H + b * H;
    for (int i = tid; i < H; i += 256) hs[i] = hp[i];
    __syncthreads();

    for (int c = warp; c < CLS; c += 8) {
        const float* wr = fcw + c * H;
        float s = 0.f;
        for (int k = lane; k < H; k += 32) s += wr[k] * hs[k];
#pragma unroll
        for (int off = 16; off > 0; off >>= 1) s += __shfl_xor_sync(0xffffffffu, s, off);
        if (lane == 0) lg[c] = s + fcb[c];
    }
    __syncthreads();

    if (tid == 0) {
        float mx = -1e30f;
        for (int c = 0; c < CLS; ++c) mx = fmaxf(mx, lg[c]);
        float se = 0.f;
        for (int c = 0; c < CLS; ++c) se += expf(lg[c] - mx);
        float lse = mx + logf(se);
        int tgt = (int)ids[b * SEQ + t + 1];
        d_nll[m] = lse - lg[tgt];
    }
}

__global__ void k_loss(const float* __restrict__ mask, float* __restrict__ out) {
    __shared__ float s1s[256], s2s[256];
    const int tid = threadIdx.x;
    float sn = 0.f, sm = 0.f;
    for (int i = tid; i < TSTEPS * BB; i += 256) sn += d_nll[i];
    for (int i = tid; i < BB * TSTEPS; i += 256) {
        int b = i / TSTEPS, t = i % TSTEPS;
        sm += mask[b * SEQ + t + 1];
    }
    s1s[tid] = sn; s2s[tid] = sm;
    __syncthreads();
    for (int o = 128; o > 0; o >>= 1) {
        if (tid < o) { s1s[tid] += s1s[tid + o]; s2s[tid] += s2s[tid + o]; }
        __syncthreads();
    }
    if (tid == 0) {
        float ce = s1s[0] / (float)(TSTEPS * BB);
        float masked = ce * s2s[0] / s2s[0];   // matches reference (incl. mask==0 -> NaN)
        out[0] = ce + masked;
    }
}

// ---------------- launch ----------------
extern "C" void kernel_launch(void* const* d_in, const int* in_sizes, int n_in,
                              void* d_out, int out_size) {
    const long long* ids  = (const long long*)d_in[0];
    const float* mask     = (const float*)d_in[1];
    const float* cond     = (const float*)d_in[2];
    const float* emb      = (const float*)d_in[3];
    const float* Wih0     = (const float*)d_in[4];
    const float* Whh0     = (const float*)d_in[5];
    const float* bih0     = (const float*)d_in[6];
    const float* bhh0     = (const float*)d_in[7];
    const float* Wih1     = (const float*)d_in[8];
    const float* Whh1     = (const float*)d_in[9];
    const float* bih1     = (const float*)d_in[10];
    const float* bhh1     = (const float*)d_in[11];
    const float* fcw      = (const float*)d_in[12];
    const float* fcb      = (const float*)d_in[13];

    static bool init = false;
    if (!init) {
        cudaFuncSetAttribute(k_recur, cudaFuncAttributeMaxDynamicSharedMemorySize,
                             (int)SMEM_TOTAL);
        init = true;
    }

    k_reset<<<32, 256>>>();
    k_pre<<<((BB + CLS + 1) * G4 + 255) / 256, 256>>>(Wih0, cond, emb, bih0, bhh0, bih1, bhh1);
    k_recur<<<NB, 256, SMEM_TOTAL>>>(ids, Whh0, Wih1, Whh1);
    k_ce<<<TSTEPS * BB, 256>>>(ids, fcw, fcb);
    k_loss<<<1, 256>>>(mask, (float*)d_out);
}